// round 2
// baseline (speedup 1.0000x reference)
#include <cuda_runtime.h>
#include <math.h>

#define BB   4096
#define TT   56
#define NSTEPS 28
#define HH   126
#define GG   378   // 3*H
#define ANN_ 30
#define ENC_ 20
#define DEC_ 15
#define DIN_ 142   // 1 + DEC + H

// ---------------- scratch (device globals; no allocations) ----------------
__device__ float g_h0[BB * HH];
__device__ float g_h1[BB * HH];
__device__ float g_enc_out[TT * BB * HH];   // 115.6 MB
__device__ float g_Uo[TT * BB * HH];        // 115.6 MB
__device__ float g_Wh[BB * HH];
__device__ float g_scores[TT * BB];
__device__ float g_x[BB * DIN_];
// transposed weights (WT[k][j] = W[j][k]) for coalesced reads
__device__ float g_encWihT[ENC_ * GG];
__device__ float g_encWhhT[HH * GG];
__device__ float g_decWihT[DIN_ * GG];
__device__ float g_decWhhT[HH * GG];
__device__ float g_UWT[HH * HH];
__device__ float g_WlT[HH * HH];

__device__ __forceinline__ float sigf(float v) { return 1.0f / (1.0f + expf(-v)); }

// ---------------- transpose: WT[c*R + r] = W[r*C + c] ----------------
__global__ void transpose_kernel(const float* __restrict__ W, float* __restrict__ WT,
                                 int R, int C) {
    int i = blockIdx.x * blockDim.x + threadIdx.x;
    if (i < R * C) {
        int r = i / C, c = i % C;
        WT[c * R + r] = W[r * C + c];
    }
}

// ---------------- s2h MLP: hidden = relu(ann@W1.T+b1)@W2.T+b2 ----------------
__global__ void s2h_kernel(const float* __restrict__ ann,
                           const float* __restrict__ W1, const float* __restrict__ b1,
                           const float* __restrict__ W2, const float* __restrict__ b2,
                           float* __restrict__ h) {
    __shared__ float a[ANN_];
    __shared__ float mid[96];
    int b = blockIdx.x;
    int tid = threadIdx.x;
    if (tid < ANN_) a[tid] = ann[b * ANN_ + tid];
    __syncthreads();
    if (tid < 96) {
        float acc = b1[tid];
        #pragma unroll
        for (int k = 0; k < ANN_; k++) acc += W1[tid * ANN_ + k] * a[k];
        mid[tid] = fmaxf(acc, 0.0f);
    }
    __syncthreads();
    if (tid < HH) {
        float acc = b2[tid];
        #pragma unroll 4
        for (int k = 0; k < 96; k++) acc += W2[tid * 96 + k] * mid[k];
        h[b * HH + tid] = acc;
    }
}

// ---------------- fused GRU step ----------------
// Block: 128 threads, thread j = output column (j<126), 16 batch rows per block.
// smem tile layout s[k*20 + r] (pad 20 keeps float4 loads 16B-aligned, low conflicts).
template <int XD>
__global__ void gru_kernel(const float* __restrict__ h_in,
                           const float* __restrict__ x,
                           const float* __restrict__ WihT,   // [XD][378]
                           const float* __restrict__ WhhT,   // [126][378]
                           const float* __restrict__ bih,
                           const float* __restrict__ bhh,
                           float* __restrict__ h_out,
                           float* __restrict__ enc_copy,     // optional
                           const float* __restrict__ h2oW,   // optional
                           const float* __restrict__ h2ob,
                           float* __restrict__ out) {        // optional
    constexpr int K = XD + HH;
    __shared__ float s[K * 20];
    __shared__ float red[4][16];
    const int tid = threadIdx.x;
    const int b0 = blockIdx.x * 16;

    // load x tile: coalesced over k
    for (int idx = tid; idx < XD * 16; idx += 128) {
        int r = idx / XD, k = idx % XD;
        s[k * 20 + r] = x[(b0 + r) * XD + k];
    }
    // load h tile
    for (int idx = tid; idx < HH * 16; idx += 128) {
        int r = idx / HH, k = idx % HH;
        s[(XD + k) * 20 + r] = h_in[(b0 + r) * HH + k];
    }
    __syncthreads();

    const int j = tid;
    float pout[16];
    if (j < HH) {
        float ar[16], az[16], ain[16], ahn[16];
        #pragma unroll
        for (int r = 0; r < 16; r++) { ar[r] = 0.f; az[r] = 0.f; ain[r] = 0.f; ahn[r] = 0.f; }

        // gi part (x @ Wih^T)
        #pragma unroll 2
        for (int k = 0; k < XD; k++) {
            float wr = WihT[k * GG + j];
            float wz = WihT[k * GG + j + HH];
            float wn = WihT[k * GG + j + 2 * HH];
            const float4* sp = reinterpret_cast<const float4*>(s + k * 20);
            #pragma unroll
            for (int q = 0; q < 4; q++) {
                float4 v = sp[q];
                ar[q*4+0] += wr * v.x; ar[q*4+1] += wr * v.y; ar[q*4+2] += wr * v.z; ar[q*4+3] += wr * v.w;
                az[q*4+0] += wz * v.x; az[q*4+1] += wz * v.y; az[q*4+2] += wz * v.z; az[q*4+3] += wz * v.w;
                ain[q*4+0] += wn * v.x; ain[q*4+1] += wn * v.y; ain[q*4+2] += wn * v.z; ain[q*4+3] += wn * v.w;
            }
        }
        // gh part (h @ Whh^T)
        #pragma unroll 2
        for (int k = 0; k < HH; k++) {
            float wr = WhhT[k * GG + j];
            float wz = WhhT[k * GG + j + HH];
            float wn = WhhT[k * GG + j + 2 * HH];
            const float4* sp = reinterpret_cast<const float4*>(s + (XD + k) * 20);
            #pragma unroll
            for (int q = 0; q < 4; q++) {
                float4 v = sp[q];
                ar[q*4+0] += wr * v.x; ar[q*4+1] += wr * v.y; ar[q*4+2] += wr * v.z; ar[q*4+3] += wr * v.w;
                az[q*4+0] += wz * v.x; az[q*4+1] += wz * v.y; az[q*4+2] += wz * v.z; az[q*4+3] += wz * v.w;
                ahn[q*4+0] += wn * v.x; ahn[q*4+1] += wn * v.y; ahn[q*4+2] += wn * v.z; ahn[q*4+3] += wn * v.w;
            }
        }

        float bir = bih[j], biz = bih[j + HH], bin = bih[j + 2 * HH];
        float bhr = bhh[j], bhz = bhh[j + HH], bhn = bhh[j + 2 * HH];
        float w_o = (out != nullptr) ? h2oW[j] : 0.f;
        #pragma unroll
        for (int r = 0; r < 16; r++) {
            float rg = sigf(ar[r] + bir + bhr);
            float zg = sigf(az[r] + biz + bhz);
            float nn = tanhf(ain[r] + bin + rg * (ahn[r] + bhn));
            float hv = s[(XD + j) * 20 + r];
            float hnew = (1.0f - zg) * nn + zg * hv;
            h_out[(b0 + r) * HH + j] = hnew;
            if (enc_copy) enc_copy[(b0 + r) * HH + j] = hnew;
            pout[r] = hnew * w_o;
        }
    } else {
        #pragma unroll
        for (int r = 0; r < 16; r++) pout[r] = 0.f;
    }

    if (out != nullptr) {
        #pragma unroll
        for (int r = 0; r < 16; r++) {
            float v = pout[r];
            #pragma unroll
            for (int off = 16; off; off >>= 1) v += __shfl_down_sync(0xffffffffu, v, off);
            if ((tid & 31) == 0) red[tid >> 5][r] = v;
        }
        __syncthreads();
        if (tid < 16) {
            out[b0 + tid] = red[0][tid] + red[1][tid] + red[2][tid] + red[3][tid] + h2ob[0];
        }
    }
}

// ---------------- generic [N,126] @ [126,126]^T + bias ----------------
__global__ void linear126_kernel(const float* __restrict__ in,
                                 const float* __restrict__ WT,   // [126][126]
                                 const float* __restrict__ bias,
                                 float* __restrict__ out) {
    __shared__ float s[HH * 20];
    const int tid = threadIdx.x;
    const int b0 = blockIdx.x * 16;
    for (int idx = tid; idx < HH * 16; idx += 128) {
        int r = idx / HH, k = idx % HH;
        s[k * 20 + r] = in[(b0 + r) * HH + k];
    }
    __syncthreads();
    const int j = tid;
    if (j < HH) {
        float acc[16];
        #pragma unroll
        for (int r = 0; r < 16; r++) acc[r] = 0.f;
        #pragma unroll 2
        for (int k = 0; k < HH; k++) {
            float w = WT[k * HH + j];
            const float4* sp = reinterpret_cast<const float4*>(s + k * 20);
            #pragma unroll
            for (int q = 0; q < 4; q++) {
                float4 v = sp[q];
                acc[q*4+0] += w * v.x; acc[q*4+1] += w * v.y; acc[q*4+2] += w * v.z; acc[q*4+3] += w * v.w;
            }
        }
        float bj = bias[j];
        #pragma unroll
        for (int r = 0; r < 16; r++) out[(b0 + r) * HH + j] = acc[r] + bj;
    }
}

// ---------------- attention scores: tanh(Uo + Wh) . V + Vb ----------------
__global__ void score_kernel(const float* __restrict__ Uo, const float* __restrict__ Wh,
                             const float* __restrict__ V, const float* __restrict__ Vb,
                             float* __restrict__ scores) {
    int w = blockIdx.x * 4 + (threadIdx.x >> 5);
    int lane = threadIdx.x & 31;
    int t = w / BB, b = w % BB;
    const float* uo = Uo + (size_t)(t * BB + b) * HH;
    const float* wh = Wh + b * HH;
    float acc = 0.f;
    #pragma unroll
    for (int m = 0; m < 4; m++) {
        int idx = lane + 32 * m;
        if (idx < HH) acc += tanhf(uo[idx] + wh[idx]) * V[idx];
    }
    #pragma unroll
    for (int off = 16; off; off >>= 1) acc += __shfl_down_sync(0xffffffffu, acc, off);
    if (lane == 0) scores[t * BB + b] = acc + Vb[0];
}

// ---------------- softmax over t (in place) + build x head ----------------
__global__ void softmax_xhead_kernel(float* __restrict__ scores,
                                     const float* __restrict__ enc_data,
                                     const float* __restrict__ dec_data,
                                     const float* __restrict__ outbuf,
                                     float* __restrict__ x, int step) {
    int b = blockIdx.x * blockDim.x + threadIdx.x;
    if (b >= BB) return;
    float mx = -1e30f;
    for (int t = 0; t < TT; t++) mx = fmaxf(mx, scores[t * BB + b]);
    float sum = 0.f;
    for (int t = 0; t < TT; t++) sum += expf(scores[t * BB + b] - mx);
    float inv = 1.0f / sum;
    for (int t = 0; t < TT; t++) scores[t * BB + b] = expf(scores[t * BB + b] - mx) * inv;
    float prev = (step == 0) ? enc_data[((TT - 1) * BB + b) * ENC_]
                             : outbuf[(step - 1) * BB + b];
    x[b * DIN_] = prev;
    #pragma unroll
    for (int i = 0; i < DEC_; i++)
        x[b * DIN_ + 1 + i] = dec_data[(step * BB + b) * DEC_ + i];
}

// ---------------- attn = sum_t alpha[t,b] * enc_out[t,b,:] -> x[:,16:142] ----
__global__ void attn_kernel(const float* __restrict__ alpha,
                            const float* __restrict__ enc_out,
                            float* __restrict__ x) {
    const int b0 = blockIdx.x * 8;
    const int j = threadIdx.x;
    float acc[8];
    #pragma unroll
    for (int r = 0; r < 8; r++) acc[r] = 0.f;
    for (int t = 0; t < TT; t++) {
        const float* eo = enc_out + ((size_t)t * BB + b0) * HH;
        const float* al = alpha + t * BB + b0;
        #pragma unroll
        for (int r = 0; r < 8; r++) {
            float a = __ldg(al + r);
            if (j < HH) acc[r] += a * eo[r * HH + j];
        }
    }
    if (j < HH) {
        #pragma unroll
        for (int r = 0; r < 8; r++)
            x[(b0 + r) * DIN_ + 1 + DEC_ + j] = acc[r];
    }
}

// ---------------- host side ----------------
extern "C" void kernel_launch(void* const* d_in, const int* in_sizes, int n_in,
                              void* d_out, int out_size) {
    const float* ann      = (const float*)d_in[0];
    const float* enc_data = (const float*)d_in[1];
    const float* dec_data = (const float*)d_in[2];
    const float* s2h_W1   = (const float*)d_in[3];
    const float* s2h_b1   = (const float*)d_in[4];
    const float* s2h_W2   = (const float*)d_in[5];
    const float* s2h_b2   = (const float*)d_in[6];
    const float* enc_Wih  = (const float*)d_in[7];
    const float* enc_Whh  = (const float*)d_in[8];
    const float* enc_bih  = (const float*)d_in[9];
    const float* enc_bhh  = (const float*)d_in[10];
    const float* dec_Wih  = (const float*)d_in[11];
    const float* dec_Whh  = (const float*)d_in[12];
    const float* dec_bih  = (const float*)d_in[13];
    const float* dec_bhh  = (const float*)d_in[14];
    const float* U_W      = (const float*)d_in[15];
    const float* U_b      = (const float*)d_in[16];
    const float* Wl_W     = (const float*)d_in[17];
    const float* Wl_b     = (const float*)d_in[18];
    const float* V_W      = (const float*)d_in[19];
    const float* V_b      = (const float*)d_in[20];
    const float* h2o_W    = (const float*)d_in[21];
    const float* h2o_b    = (const float*)d_in[22];
    float* outp = (float*)d_out;

    float *h0, *h1, *enc_out, *Uo, *Wh, *scores, *x;
    float *eWihT, *eWhhT, *dWihT, *dWhhT, *UWT, *WlT;
    cudaGetSymbolAddress((void**)&h0, g_h0);
    cudaGetSymbolAddress((void**)&h1, g_h1);
    cudaGetSymbolAddress((void**)&enc_out, g_enc_out);
    cudaGetSymbolAddress((void**)&Uo, g_Uo);
    cudaGetSymbolAddress((void**)&Wh, g_Wh);
    cudaGetSymbolAddress((void**)&scores, g_scores);
    cudaGetSymbolAddress((void**)&x, g_x);
    cudaGetSymbolAddress((void**)&eWihT, g_encWihT);
    cudaGetSymbolAddress((void**)&eWhhT, g_encWhhT);
    cudaGetSymbolAddress((void**)&dWihT, g_decWihT);
    cudaGetSymbolAddress((void**)&dWhhT, g_decWhhT);
    cudaGetSymbolAddress((void**)&UWT, g_UWT);
    cudaGetSymbolAddress((void**)&WlT, g_WlT);

    // one-time weight transposes
    transpose_kernel<<<(GG * ENC_ + 255) / 256, 256>>>(enc_Wih, eWihT, GG, ENC_);
    transpose_kernel<<<(GG * HH + 255) / 256, 256>>>(enc_Whh, eWhhT, GG, HH);
    transpose_kernel<<<(GG * DIN_ + 255) / 256, 256>>>(dec_Wih, dWihT, GG, DIN_);
    transpose_kernel<<<(GG * HH + 255) / 256, 256>>>(dec_Whh, dWhhT, GG, HH);
    transpose_kernel<<<(HH * HH + 255) / 256, 256>>>(U_W, UWT, HH, HH);
    transpose_kernel<<<(HH * HH + 255) / 256, 256>>>(Wl_W, WlT, HH, HH);

    // initial hidden
    s2h_kernel<<<BB, 128>>>(ann, s2h_W1, s2h_b1, s2h_W2, s2h_b2, h0);

    // encoder scan
    for (int t = 0; t < TT; t++) {
        const float* hin = (t % 2 == 0) ? h0 : h1;
        float* hout      = (t % 2 == 0) ? h1 : h0;
        gru_kernel<ENC_><<<BB / 16, 128>>>(hin, enc_data + (size_t)t * BB * ENC_,
                                           eWihT, eWhhT, enc_bih, enc_bhh,
                                           hout, enc_out + (size_t)t * BB * HH,
                                           nullptr, nullptr, nullptr);
    }
    // final encoder h is in h0 (56 even)

    // Uo = enc_out @ U_W^T + U_b
    linear126_kernel<<<(TT * BB) / 16, 128>>>(enc_out, UWT, U_b, Uo);

    // decoder scan
    for (int s = 0; s < NSTEPS; s++) {
        const float* hcur = (s % 2 == 0) ? h0 : h1;
        float* hnext      = (s % 2 == 0) ? h1 : h0;
        linear126_kernel<<<BB / 16, 128>>>(hcur, WlT, Wl_b, Wh);
        score_kernel<<<(TT * BB) / 4, 128>>>(Uo, Wh, V_W, V_b, scores);
        softmax_xhead_kernel<<<BB / 256, 256>>>(scores, enc_data, dec_data, outp, x, s);
        attn_kernel<<<BB / 8, 128>>>(scores, enc_out, x);
        gru_kernel<DIN_><<<BB / 16, 128>>>(hcur, x, dWihT, dWhhT, dec_bih, dec_bhh,
                                           hnext, nullptr, h2o_W, h2o_b, outp + s * BB);
    }
}

// round 3
// speedup vs baseline: 1.0640x; 1.0640x over previous
#include <cuda_runtime.h>
#include <math.h>

#define BB   4096
#define TT   56
#define NSTEPS 28
#define HH   126
#define GG   378   // 3*H
#define ANN_ 30
#define ENC_ 20
#define DEC_ 15
#define DIN_ 142   // 1 + DEC + H

#define GRU_ROWS 14
#define GRU_GRID ((BB + GRU_ROWS - 1) / GRU_ROWS)   // 293

// ---------------- scratch (device globals; no allocations) ----------------
__device__ float g_h0[BB * HH];
__device__ float g_h1[BB * HH];
__device__ float g_enc_out[TT * BB * HH];   // 115.6 MB
__device__ float g_Uo[TT * BB * HH];        // 115.6 MB
__device__ float g_x[BB * DIN_];
__device__ float g_Wenc[(ENC_ + HH) * GG];  // [146][378]
__device__ float g_Wdec[(DIN_ + HH) * GG];  // [268][378]
__device__ float g_UWT[HH * HH];
__device__ float g_WlT[HH * HH];

// ---------------- fast transcendentals (MUFU, ~1e-6) ----------------
__device__ __forceinline__ float ex2f(float x) { float y; asm("ex2.approx.f32 %0, %1;" : "=f"(y) : "f"(x)); return y; }
__device__ __forceinline__ float rcpf(float x) { float y; asm("rcp.approx.f32 %0, %1;" : "=f"(y) : "f"(x)); return y; }
#define LOG2E_ 1.4426950408889634f
__device__ __forceinline__ float sigf(float v)  { return rcpf(1.0f + ex2f(-v * LOG2E_)); }
__device__ __forceinline__ float tanhp(float v) { return 2.0f * rcpf(1.0f + ex2f(-2.0f * v * LOG2E_)) - 1.0f; }

// ---------------- fused weight prep: 1 launch ----------------
__global__ void prep_weights(const float* __restrict__ eWih, const float* __restrict__ eWhh,
                             const float* __restrict__ dWih, const float* __restrict__ dWhh,
                             const float* __restrict__ U,    const float* __restrict__ Wl) {
    int i = blockIdx.x * 256 + threadIdx.x;
    const int N1 = (ENC_ + HH) * GG;      // 146*378
    const int N2 = (DIN_ + HH) * GG;      // 268*378
    const int N3 = HH * HH;
    if (i < N1) {
        int k = i / GG, j = i % GG;
        g_Wenc[i] = (k < ENC_) ? eWih[j * ENC_ + k] : eWhh[j * HH + (k - ENC_)];
        return;
    }
    i -= N1;
    if (i < N2) {
        int k = i / GG, j = i % GG;
        g_Wdec[i] = (k < DIN_) ? dWih[j * DIN_ + k] : dWhh[j * HH + (k - DIN_)];
        return;
    }
    i -= N2;
    if (i < N3) { int k = i / HH, j = i % HH; g_UWT[i] = U[j * HH + k]; return; }
    i -= N3;
    if (i < N3) { int k = i / HH, j = i % HH; g_WlT[i] = Wl[j * HH + k]; }
}

// ---------------- s2h MLP ----------------
__global__ void s2h_kernel(const float* __restrict__ ann,
                           const float* __restrict__ W1, const float* __restrict__ b1,
                           const float* __restrict__ W2, const float* __restrict__ b2,
                           float* __restrict__ h) {
    __shared__ float a[ANN_];
    __shared__ float mid[96];
    int b = blockIdx.x;
    int tid = threadIdx.x;
    if (tid < ANN_) a[tid] = ann[b * ANN_ + tid];
    __syncthreads();
    if (tid < 96) {
        float acc = b1[tid];
        #pragma unroll
        for (int k = 0; k < ANN_; k++) acc += W1[tid * ANN_ + k] * a[k];
        mid[tid] = fmaxf(acc, 0.0f);
    }
    __syncthreads();
    if (tid < HH) {
        float acc = b2[tid];
        #pragma unroll 4
        for (int k = 0; k < 96; k++) acc += W2[tid * 96 + k] * mid[k];
        h[b * HH + tid] = acc;
    }
}

// ---------------- fused GRU step ----------------
// 384 threads; thread j computes gate-column j of the [B,378] pre-activation GEMM
// over K = XD + 126, for GRU_ROWS batch rows. Epilogue fuses gates + optional h2o.
template <int XD, bool IS_DEC>
__global__ __launch_bounds__(384) void gru2_kernel(
        const float* __restrict__ h_in,
        const float* __restrict__ x,
        const float* __restrict__ Wcat,   // [(XD+126)][378]
        const float* __restrict__ bih, const float* __restrict__ bhh,
        float* __restrict__ h_out,
        const float* __restrict__ h2oW, const float* __restrict__ h2ob,
        float* __restrict__ out) {
    constexpr int K  = XD + HH;
    constexpr int RP = 16;   // tile pitch (float4 aligned)
    constexpr int PP = 15;   // preact pitch (conflict-free)
    __shared__ float s_in[K * RP];
    __shared__ float s_pre[GG * PP];
    __shared__ float s_nx[HH * PP];
    __shared__ float s_out[GRU_ROWS];

    const int tid = threadIdx.x;
    const int b0 = blockIdx.x * GRU_ROWS;
    const int nrow = min(GRU_ROWS, BB - b0);

    if (IS_DEC && tid < GRU_ROWS) s_out[tid] = 0.0f;

    // load x tile (coalesced over k)
    for (int idx = tid; idx < XD * GRU_ROWS; idx += 384) {
        int r = idx / XD, k = idx % XD;
        s_in[k * RP + r] = (r < nrow) ? x[(size_t)(b0 + r) * XD + k] : 0.0f;
    }
    // load h tile
    for (int idx = tid; idx < HH * GRU_ROWS; idx += 384) {
        int r = idx / HH, k = idx % HH;
        s_in[(XD + k) * RP + r] = (r < nrow) ? h_in[(size_t)(b0 + r) * HH + k] : 0.0f;
    }
    __syncthreads();

    const int jj = min(tid, GG - 1);
    float acc[GRU_ROWS];
    #pragma unroll
    for (int r = 0; r < GRU_ROWS; r++) acc[r] = 0.0f;

    // ---- x part ----
    #pragma unroll 2
    for (int k = 0; k < XD; k++) {
        float w = Wcat[k * GG + jj];
        const float4* sp = reinterpret_cast<const float4*>(s_in + k * RP);
        float4 v0 = sp[0], v1 = sp[1], v2 = sp[2];
        float2 v3 = *reinterpret_cast<const float2*>(s_in + k * RP + 12);
        acc[0]  += w * v0.x; acc[1]  += w * v0.y; acc[2]  += w * v0.z; acc[3]  += w * v0.w;
        acc[4]  += w * v1.x; acc[5]  += w * v1.y; acc[6]  += w * v1.z; acc[7]  += w * v1.w;
        acc[8]  += w * v2.x; acc[9]  += w * v2.y; acc[10] += w * v2.z; acc[11] += w * v2.w;
        acc[12] += w * v3.x; acc[13] += w * v3.y;
    }
    // snapshot x-part for n-gate (needed separately: n = tanh(inn + r*hn))
    if (tid >= 2 * HH && tid < GG) {
        #pragma unroll
        for (int r = 0; r < GRU_ROWS; r++) s_nx[(tid - 2 * HH) * PP + r] = acc[r];
    }
    // ---- h part ----
    #pragma unroll 2
    for (int k = XD; k < K; k++) {
        float w = Wcat[k * GG + jj];
        const float4* sp = reinterpret_cast<const float4*>(s_in + k * RP);
        float4 v0 = sp[0], v1 = sp[1], v2 = sp[2];
        float2 v3 = *reinterpret_cast<const float2*>(s_in + k * RP + 12);
        acc[0]  += w * v0.x; acc[1]  += w * v0.y; acc[2]  += w * v0.z; acc[3]  += w * v0.w;
        acc[4]  += w * v1.x; acc[5]  += w * v1.y; acc[6]  += w * v1.z; acc[7]  += w * v1.w;
        acc[8]  += w * v2.x; acc[9]  += w * v2.y; acc[10] += w * v2.z; acc[11] += w * v2.w;
        acc[12] += w * v3.x; acc[13] += w * v3.y;
    }
    if (tid < GG) {
        #pragma unroll
        for (int r = 0; r < GRU_ROWS; r++) s_pre[tid * PP + r] = acc[r];
    }
    __syncthreads();

    // ---- epilogue: gates ----
    for (int idx = tid; idx < HH * nrow; idx += 384) {
        int j = idx % HH;
        int r = idx / HH;
        float pre_r = s_pre[j * PP + r]            + bih[j]          + bhh[j];
        float pre_z = s_pre[(HH + j) * PP + r]     + bih[HH + j]     + bhh[HH + j];
        float inn   = s_nx[j * PP + r]             + bih[2 * HH + j];
        float hn    = (s_pre[(2 * HH + j) * PP + r] - s_nx[j * PP + r]) + bhh[2 * HH + j];
        float rg = sigf(pre_r);
        float zg = sigf(pre_z);
        float nn = tanhp(inn + rg * hn);
        float hv = h_in[(size_t)(b0 + r) * HH + j];   // coalesced reload (L2 hit)
        float hnew = (1.0f - zg) * nn + zg * hv;
        h_out[(size_t)(b0 + r) * HH + j] = hnew;
        if (IS_DEC) atomicAdd(&s_out[r], hnew * h2oW[j]);
    }
    if (IS_DEC) {
        __syncthreads();
        if (tid < nrow) out[b0 + tid] = s_out[tid] + h2ob[0];
    }
}

// ---------------- Uo = enc_out @ U_W^T + U_b ----------------
__global__ void linear126_kernel(const float* __restrict__ in,
                                 const float* __restrict__ WT,
                                 const float* __restrict__ bias,
                                 float* __restrict__ out) {
    __shared__ float s[HH * 20];
    const int tid = threadIdx.x;
    const int b0 = blockIdx.x * 16;
    for (int idx = tid; idx < HH * 16; idx += 128) {
        int r = idx / HH, k = idx % HH;
        s[k * 20 + r] = in[(size_t)(b0 + r) * HH + k];
    }
    __syncthreads();
    const int j = tid;
    if (j < HH) {
        float acc[16];
        #pragma unroll
        for (int r = 0; r < 16; r++) acc[r] = 0.f;
        #pragma unroll 2
        for (int k = 0; k < HH; k++) {
            float w = WT[k * HH + j];
            const float4* sp = reinterpret_cast<const float4*>(s + k * 20);
            #pragma unroll
            for (int q = 0; q < 4; q++) {
                float4 v = sp[q];
                acc[q*4+0] += w * v.x; acc[q*4+1] += w * v.y;
                acc[q*4+2] += w * v.z; acc[q*4+3] += w * v.w;
            }
        }
        float bj = bias[j];
        #pragma unroll
        for (int r = 0; r < 16; r++) out[(size_t)(b0 + r) * HH + j] = acc[r] + bj;
    }
}

// ---------------- fused decoder attention ----------------
// Per block: 16 batch rows, 256 threads.
// Phase 0: Wh = h @ WlT + Wl_b (smem GEMM)
// Phase 1: scores[t] = V . tanh(Uo[t] + Wh) + Vb   (streams Uo once)
// Phase 2: softmax over t; assemble x[:,0:16] (prev output + decoder features)
// Phase 3: x[:,16:142] = sum_t alpha[t] * enc_out[t]  (streams enc_out once)
__global__ __launch_bounds__(256) void attn_fused_kernel(
        const float* __restrict__ h,
        const float* __restrict__ Uo, const float* __restrict__ enc_out,
        const float* __restrict__ WlT, const float* __restrict__ Wl_b,
        const float* __restrict__ V, const float* __restrict__ Vb,
        const float* __restrict__ enc_data, const float* __restrict__ dec_data,
        const float* __restrict__ outbuf,
        float* __restrict__ x, int step) {
    __shared__ float sh[HH * 16];     // h tile, k-major
    __shared__ float swh[HH * 17];    // Wh[c][r]
    __shared__ float sc[TT * 17];     // scores -> alpha

    const int tid = threadIdx.x;
    const int b0 = blockIdx.x * 16;
    const int jc = tid & 127;
    const int half = tid >> 7;

    for (int idx = tid; idx < HH * 16; idx += 256) {
        int r = idx / HH, k = idx % HH;
        sh[k * 16 + r] = h[(size_t)(b0 + r) * HH + k];
    }
    __syncthreads();

    // Phase 0: Wh
    if (jc < HH) {
        float acc[8];
        #pragma unroll
        for (int q = 0; q < 8; q++) acc[q] = 0.f;
        #pragma unroll 2
        for (int k = 0; k < HH; k++) {
            float w = WlT[k * HH + jc];
            const float4* sp = reinterpret_cast<const float4*>(sh + k * 16) + half * 2;
            float4 v0 = sp[0], v1 = sp[1];
            acc[0] += w * v0.x; acc[1] += w * v0.y; acc[2] += w * v0.z; acc[3] += w * v0.w;
            acc[4] += w * v1.x; acc[5] += w * v1.y; acc[6] += w * v1.z; acc[7] += w * v1.w;
        }
        float bj = Wl_b[jc];
        #pragma unroll
        for (int q = 0; q < 8; q++) swh[jc * 17 + half * 8 + q] = acc[q] + bj;
    }
    __syncthreads();

    // Phase 1: scores
    {
        const int warp = tid >> 5, lane = tid & 31;
        const float vb = Vb[0];
        for (int t = 0; t < TT; t++) {
            #pragma unroll
            for (int rr = 0; rr < 2; rr++) {
                int r = warp * 2 + rr;
                const float* uo = Uo + ((size_t)t * BB + b0 + r) * HH;
                float a = 0.f;
                #pragma unroll
                for (int m = 0; m < 4; m++) {
                    int c = lane + 32 * m;
                    if (c < HH) a += tanhp(uo[c] + swh[c * 17 + r]) * V[c];
                }
                #pragma unroll
                for (int off = 16; off; off >>= 1) a += __shfl_down_sync(0xffffffffu, a, off);
                if (lane == 0) sc[t * 17 + r] = a + vb;
            }
        }
    }
    __syncthreads();

    // Phase 2: softmax over t per row; build x head
    if (tid < 16) {
        int r = tid;
        float mx = -1e30f;
        for (int t = 0; t < TT; t++) mx = fmaxf(mx, sc[t * 17 + r]);
        float sum = 0.f;
        for (int t = 0; t < TT; t++) {
            float e = ex2f((sc[t * 17 + r] - mx) * LOG2E_);
            sc[t * 17 + r] = e;
            sum += e;
        }
        float inv = rcpf(sum);
        for (int t = 0; t < TT; t++) sc[t * 17 + r] *= inv;
        float prev = (step == 0) ? enc_data[((size_t)(TT - 1) * BB + b0 + r) * ENC_]
                                 : outbuf[(size_t)(step - 1) * BB + b0 + r];
        x[(size_t)(b0 + r) * DIN_] = prev;
    } else if (tid < 16 + 240) {
        int i2 = tid - 16;
        int r = i2 / DEC_, c = i2 % DEC_;
        x[(size_t)(b0 + r) * DIN_ + 1 + c] = dec_data[((size_t)step * BB + b0 + r) * DEC_ + c];
    }
    __syncthreads();

    // Phase 3: attn accumulation
    if (jc < HH) {
        float acc[8];
        #pragma unroll
        for (int q = 0; q < 8; q++) acc[q] = 0.f;
        for (int t = 0; t < TT; t++) {
            const float* eo = enc_out + ((size_t)t * BB + b0 + half * 8) * HH + jc;
            #pragma unroll
            for (int q = 0; q < 8; q++) {
                float a = sc[t * 17 + half * 8 + q];
                acc[q] += a * eo[(size_t)q * HH];
            }
        }
        #pragma unroll
        for (int q = 0; q < 8; q++)
            x[(size_t)(b0 + half * 8 + q) * DIN_ + 1 + DEC_ + jc] = acc[q];
    }
}

// ---------------- host side ----------------
extern "C" void kernel_launch(void* const* d_in, const int* in_sizes, int n_in,
                              void* d_out, int out_size) {
    const float* ann      = (const float*)d_in[0];
    const float* enc_data = (const float*)d_in[1];
    const float* dec_data = (const float*)d_in[2];
    const float* s2h_W1   = (const float*)d_in[3];
    const float* s2h_b1   = (const float*)d_in[4];
    const float* s2h_W2   = (const float*)d_in[5];
    const float* s2h_b2   = (const float*)d_in[6];
    const float* enc_Wih  = (const float*)d_in[7];
    const float* enc_Whh  = (const float*)d_in[8];
    const float* enc_bih  = (const float*)d_in[9];
    const float* enc_bhh  = (const float*)d_in[10];
    const float* dec_Wih  = (const float*)d_in[11];
    const float* dec_Whh  = (const float*)d_in[12];
    const float* dec_bih  = (const float*)d_in[13];
    const float* dec_bhh  = (const float*)d_in[14];
    const float* U_W      = (const float*)d_in[15];
    const float* U_b      = (const float*)d_in[16];
    const float* Wl_W     = (const float*)d_in[17];
    const float* Wl_b     = (const float*)d_in[18];
    const float* V_W      = (const float*)d_in[19];
    const float* V_b      = (const float*)d_in[20];
    const float* h2o_W    = (const float*)d_in[21];
    const float* h2o_b    = (const float*)d_in[22];
    float* outp = (float*)d_out;

    float *h0, *h1, *enc_out, *Uo, *x, *Wenc, *Wdec, *UWT, *WlT;
    cudaGetSymbolAddress((void**)&h0, g_h0);
    cudaGetSymbolAddress((void**)&h1, g_h1);
    cudaGetSymbolAddress((void**)&enc_out, g_enc_out);
    cudaGetSymbolAddress((void**)&Uo, g_Uo);
    cudaGetSymbolAddress((void**)&x, g_x);
    cudaGetSymbolAddress((void**)&Wenc, g_Wenc);
    cudaGetSymbolAddress((void**)&Wdec, g_Wdec);
    cudaGetSymbolAddress((void**)&UWT, g_UWT);
    cudaGetSymbolAddress((void**)&WlT, g_WlT);

    const int total_w = (ENC_ + HH) * GG + (DIN_ + HH) * GG + 2 * HH * HH;
    prep_weights<<<(total_w + 255) / 256, 256>>>(enc_Wih, enc_Whh, dec_Wih, dec_Whh, U_W, Wl_W);

    s2h_kernel<<<BB, 128>>>(ann, s2h_W1, s2h_b1, s2h_W2, s2h_b2, h0);

    // encoder: hidden for step t written directly into enc_out[t]
    for (int t = 0; t < TT; t++) {
        const float* hin = (t == 0) ? h0 : enc_out + (size_t)(t - 1) * BB * HH;
        gru2_kernel<ENC_, false><<<GRU_GRID, 384>>>(
            hin, enc_data + (size_t)t * BB * ENC_, Wenc, enc_bih, enc_bhh,
            enc_out + (size_t)t * BB * HH, nullptr, nullptr, nullptr);
    }

    linear126_kernel<<<(TT * BB) / 16, 128>>>(enc_out, UWT, U_b, Uo);

    const float* enc_last = enc_out + (size_t)(TT - 1) * BB * HH;
    for (int s = 0; s < NSTEPS; s++) {
        const float* hcur = (s == 0) ? enc_last : ((s & 1) ? h0 : h1);
        float* hnext      = (s & 1) ? h1 : h0;
        attn_fused_kernel<<<BB / 16, 256>>>(hcur, Uo, enc_out, WlT, Wl_b, V_W, V_b,
                                            enc_data, dec_data, outp, x, s);
        gru2_kernel<DIN_, true><<<GRU_GRID, 384>>>(
            hcur, x, Wdec, dec_bih, dec_bhh, hnext, h2o_W, h2o_b, outp + (size_t)s * BB);
    }
}

// round 4
// speedup vs baseline: 1.1583x; 1.0887x over previous
#include <cuda_runtime.h>
#include <math.h>

#define BB   4096
#define TT   56
#define NSTEPS 28
#define HH   126
#define GG   378   // 3*H
#define ANN_ 30
#define ENC_ 20
#define DEC_ 15
#define DIN_ 142   // 1 + DEC + H

// padded GRU weight layouts: [KP][384], x rows [0,XD), zeros [XD,XDP),
// h rows [XDP, XDP+126), zeros to KP (KP multiple of 8)
#define XDP_E 24
#define KP_E  152
#define XDP_D 144
#define KP_D  272

// ---------------- scratch (device globals; no allocations) ----------------
__device__ float g_h0[BB * HH];
__device__ float g_h1[BB * HH];
__device__ float g_enc_out[TT * BB * HH];
__device__ float g_Uo[TT * BB * HH];
__device__ float g_x[BB * DIN_];
__device__ float g_Wenc[KP_E * 384];
__device__ float g_Wdec[KP_D * 384];
__device__ float g_UWTp[HH * 128];
__device__ float g_WlT[HH * HH];

// ---------------- fast transcendentals (MUFU, ~1e-6) ----------------
__device__ __forceinline__ float ex2f(float x) { float y; asm("ex2.approx.f32 %0, %1;" : "=f"(y) : "f"(x)); return y; }
__device__ __forceinline__ float rcpf(float x) { float y; asm("rcp.approx.f32 %0, %1;" : "=f"(y) : "f"(x)); return y; }
#define LOG2E_ 1.4426950408889634f
__device__ __forceinline__ float sigf(float v)  { return rcpf(1.0f + ex2f(-v * LOG2E_)); }
__device__ __forceinline__ float tanhp(float v) { return 2.0f * rcpf(1.0f + ex2f(-2.0f * v * LOG2E_)) - 1.0f; }

// ---------------- weight prep (padded layouts), 1 launch ----------------
__global__ void prep_weights(const float* __restrict__ eWih, const float* __restrict__ eWhh,
                             const float* __restrict__ dWih, const float* __restrict__ dWhh,
                             const float* __restrict__ U,    const float* __restrict__ Wl) {
    int i = blockIdx.x * 256 + threadIdx.x;
    const int N1 = KP_E * 384;
    const int N2 = KP_D * 384;
    const int N3 = HH * 128;
    const int N4 = HH * HH;
    if (i < N1) {
        int k = i / 384, j = i % 384;
        float v = 0.0f;
        if (j < GG) {
            if (k < ENC_) v = eWih[j * ENC_ + k];
            else if (k >= XDP_E && k < XDP_E + HH) v = eWhh[j * HH + (k - XDP_E)];
        }
        g_Wenc[i] = v; return;
    }
    i -= N1;
    if (i < N2) {
        int k = i / 384, j = i % 384;
        float v = 0.0f;
        if (j < GG) {
            if (k < DIN_) v = dWih[j * DIN_ + k];
            else if (k >= XDP_D && k < XDP_D + HH) v = dWhh[j * HH + (k - XDP_D)];
        }
        g_Wdec[i] = v; return;
    }
    i -= N2;
    if (i < N3) {
        int k = i / 128, j = i % 128;
        g_UWTp[i] = (j < HH) ? U[j * HH + k] : 0.0f;
        return;
    }
    i -= N3;
    if (i < N4) { int k = i / HH, j = i % HH; g_WlT[i] = Wl[j * HH + k]; }
}

// ---------------- s2h MLP ----------------
__global__ void s2h_kernel(const float* __restrict__ ann,
                           const float* __restrict__ W1, const float* __restrict__ b1,
                           const float* __restrict__ W2, const float* __restrict__ b2,
                           float* __restrict__ h) {
    __shared__ float a[ANN_];
    __shared__ float mid[96];
    int b = blockIdx.x;
    int tid = threadIdx.x;
    if (tid < ANN_) a[tid] = ann[b * ANN_ + tid];
    __syncthreads();
    if (tid < 96) {
        float acc = b1[tid];
        #pragma unroll
        for (int k = 0; k < ANN_; k++) acc += W1[tid * ANN_ + k] * a[k];
        mid[tid] = fmaxf(acc, 0.0f);
    }
    __syncthreads();
    if (tid < HH) {
        float acc = b2[tid];
        #pragma unroll 4
        for (int k = 0; k < 96; k++) acc += W2[tid * 96 + k] * mid[k];
        h[b * HH + tid] = acc;
    }
}

// ---------------- GRU step, smem-staged weights, double buffered ----------------
// 384 threads, 16 batch rows/block, grid 256 (one wave at 2 blocks/SM).
template <int XD, int XDP, int KP, bool IS_DEC>
__global__ __launch_bounds__(384, 2) void gru3_kernel(
        const float* __restrict__ h_in,
        const float* __restrict__ x,
        const float* __restrict__ W,      // [KP][384] padded
        const float* __restrict__ bih, const float* __restrict__ bhh,
        float* __restrict__ h_out,
        const float* __restrict__ h2oW, const float* __restrict__ h2ob,
        float* __restrict__ out) {
    constexpr int NC = KP / 8;
    constexpr int XC = XDP / 8;
    constexpr int PIN = 20;           // s_in pitch (4-way STS conflicts only, float4 aligned)
    extern __shared__ float sm[];
    float* s_in   = sm;               // KP*20
    float* pool   = sm + KP * PIN;    // max(2*3072 wbuf, 378*17 + 126*17)
    float* s_preA = pool;             // 378*17
    float* s_preB = pool + GG * 17;   // 126*17
    float* s_out  = pool + GG * 17 + HH * 17;  // 16

    const int tid = threadIdx.x;
    const int b0 = blockIdx.x * 16;

    if (IS_DEC && tid < 16) s_out[tid] = 0.0f;

    // fill s_in: x rows, h rows, zero pads
    for (int idx = tid; idx < XD * 16; idx += 384) {
        int r = idx / XD, k = idx % XD;
        s_in[k * PIN + r] = x[(size_t)(b0 + r) * XD + k];
    }
    for (int idx = tid; idx < HH * 16; idx += 384) {
        int r = idx / HH, k = idx % HH;
        s_in[(XDP + k) * PIN + r] = h_in[(size_t)(b0 + r) * HH + k];
    }
    for (int idx = tid; idx < (XDP - XD) * 16; idx += 384) {
        int k = idx / 16, r = idx % 16;
        s_in[(XD + k) * PIN + r] = 0.0f;
    }
    for (int idx = tid; idx < (KP - XDP - HH) * 16; idx += 384) {
        int k = idx / 16, r = idx % 16;
        s_in[(XDP + HH + k) * PIN + r] = 0.0f;
    }
    // preload weight chunk 0
    {
        const float4* src = reinterpret_cast<const float4*>(W);
        float4* dst = reinterpret_cast<float4*>(pool);
        dst[tid] = src[tid];
        dst[tid + 384] = src[tid + 384];
    }
    __syncthreads();

    float acc[16], accx[16];
    #pragma unroll
    for (int r = 0; r < 16; r++) { acc[r] = 0.0f; accx[r] = 0.0f; }

    for (int c = 0; c < NC; c++) {
        const int cur = c & 1;
        if (c + 1 < NC) {
            const float4* src = reinterpret_cast<const float4*>(W + (size_t)(c + 1) * 8 * 384);
            float4* dst = reinterpret_cast<float4*>(pool + (1 - cur) * 3072);
            dst[tid] = src[tid];
            dst[tid + 384] = src[tid + 384];
        }
        const float* wp = pool + cur * 3072 + tid;
        const float* ip = s_in + c * 8 * PIN;
        #pragma unroll
        for (int kk = 0; kk < 8; kk++) {
            float w = wp[kk * 384];
            const float4* sp = reinterpret_cast<const float4*>(ip + kk * PIN);
            float4 v0 = sp[0], v1 = sp[1], v2 = sp[2], v3 = sp[3];
            acc[0]  += w * v0.x; acc[1]  += w * v0.y; acc[2]  += w * v0.z; acc[3]  += w * v0.w;
            acc[4]  += w * v1.x; acc[5]  += w * v1.y; acc[6]  += w * v1.z; acc[7]  += w * v1.w;
            acc[8]  += w * v2.x; acc[9]  += w * v2.y; acc[10] += w * v2.z; acc[11] += w * v2.w;
            acc[12] += w * v3.x; acc[13] += w * v3.y; acc[14] += w * v3.z; acc[15] += w * v3.w;
        }
        if (c == XC - 1) {
            #pragma unroll
            for (int r = 0; r < 16; r++) accx[r] = acc[r];
        }
        __syncthreads();
    }

    // transpose preacts through smem (pool region now free)
    if (tid < GG) {
        #pragma unroll
        for (int r = 0; r < 16; r++) s_preA[tid * 17 + r] = acc[r];
    }
    if (tid >= 2 * HH && tid < GG) {
        #pragma unroll
        for (int r = 0; r < 16; r++) s_preB[(tid - 2 * HH) * 17 + r] = accx[r];
    }
    __syncthreads();

    // gates epilogue
    for (int idx = tid; idx < HH * 16; idx += 384) {
        int j = idx % HH;
        int r = idx / HH;
        float pre_r = s_preA[j * 17 + r]            + bih[j]          + bhh[j];
        float pre_z = s_preA[(HH + j) * 17 + r]     + bih[HH + j]     + bhh[HH + j];
        float nx    = s_preB[j * 17 + r]            + bih[2 * HH + j];
        float nh    = (s_preA[(2 * HH + j) * 17 + r] - s_preB[j * 17 + r]) + bhh[2 * HH + j];
        float rg = sigf(pre_r);
        float zg = sigf(pre_z);
        float nn = tanhp(nx + rg * nh);
        float hv = s_in[(XDP + j) * PIN + r];
        float hnew = (1.0f - zg) * nn + zg * hv;
        h_out[(size_t)(b0 + r) * HH + j] = hnew;
        if (IS_DEC) atomicAdd(&s_out[r], hnew * h2oW[j]);
    }
    if (IS_DEC) {
        __syncthreads();
        if (tid < 16) out[b0 + tid] = s_out[tid] + h2ob[0];
    }
}

// ---------------- Uo = enc_out @ U^T + b; weights resident in smem ----------------
__global__ __launch_bounds__(256, 2) void uo_kernel(const float* __restrict__ in,
                                                    const float* __restrict__ Wp,   // [126][128]
                                                    const float* __restrict__ bias,
                                                    float* __restrict__ out) {
    constexpr int PIN = 36;  // pitch: 4-way STS conflicts, float4 aligned (36*4=144)
    extern __shared__ float sm[];
    float* s_w  = sm;              // 126*128
    float* s_in = sm + HH * 128;   // 126*36
    const int tid = threadIdx.x;
    const int b0 = blockIdx.x * 32;

    {
        const float4* src = reinterpret_cast<const float4*>(Wp);
        float4* dst = reinterpret_cast<float4*>(s_w);
        for (int v = tid; v < HH * 128 / 4; v += 256) dst[v] = src[v];
    }
    for (int idx = tid; idx < HH * 32; idx += 256) {
        int r = idx / HH, k = idx % HH;
        s_in[k * PIN + r] = in[(size_t)(b0 + r) * HH + k];
    }
    __syncthreads();

    const int j = tid & 127;
    const int half = tid >> 7;
    float acc[16];
    #pragma unroll
    for (int r = 0; r < 16; r++) acc[r] = 0.0f;
    #pragma unroll 2
    for (int k = 0; k < HH; k++) {
        float w = s_w[k * 128 + j];
        const float4* sp = reinterpret_cast<const float4*>(s_in + k * PIN + half * 16);
        float4 v0 = sp[0], v1 = sp[1], v2 = sp[2], v3 = sp[3];
        acc[0]  += w * v0.x; acc[1]  += w * v0.y; acc[2]  += w * v0.z; acc[3]  += w * v0.w;
        acc[4]  += w * v1.x; acc[5]  += w * v1.y; acc[6]  += w * v1.z; acc[7]  += w * v1.w;
        acc[8]  += w * v2.x; acc[9]  += w * v2.y; acc[10] += w * v2.z; acc[11] += w * v2.w;
        acc[12] += w * v3.x; acc[13] += w * v3.y; acc[14] += w * v3.z; acc[15] += w * v3.w;
    }
    if (j < HH) {
        float bj = bias[j];
        #pragma unroll
        for (int r = 0; r < 16; r++)
            out[(size_t)(b0 + half * 16 + r) * HH + j] = acc[r] + bj;
    }
}

// ---------------- fused decoder attention ----------------
__global__ __launch_bounds__(256) void attn_fused_kernel(
        const float* __restrict__ h,
        const float* __restrict__ Uo, const float* __restrict__ enc_out,
        const float* __restrict__ WlT, const float* __restrict__ Wl_b,
        const float* __restrict__ V, const float* __restrict__ Vb,
        const float* __restrict__ enc_data, const float* __restrict__ dec_data,
        const float* __restrict__ outbuf,
        float* __restrict__ x, int step) {
    __shared__ float sh[HH * 16];     // h tile, k-major
    __shared__ float swh[HH * 17];    // Wh[c][r]
    __shared__ float sc[TT * 17];     // scores -> alpha

    const int tid = threadIdx.x;
    const int b0 = blockIdx.x * 16;
    const int jc = tid & 127;
    const int half = tid >> 7;

    for (int idx = tid; idx < HH * 16; idx += 256) {
        int r = idx / HH, k = idx % HH;
        sh[k * 16 + r] = h[(size_t)(b0 + r) * HH + k];
    }
    __syncthreads();

    // Phase 0: Wh = h @ WlT + b
    if (jc < HH) {
        float acc[8];
        #pragma unroll
        for (int q = 0; q < 8; q++) acc[q] = 0.f;
        #pragma unroll 2
        for (int k = 0; k < HH; k++) {
            float w = WlT[k * HH + jc];
            const float4* sp = reinterpret_cast<const float4*>(sh + k * 16) + half * 2;
            float4 v0 = sp[0], v1 = sp[1];
            acc[0] += w * v0.x; acc[1] += w * v0.y; acc[2] += w * v0.z; acc[3] += w * v0.w;
            acc[4] += w * v1.x; acc[5] += w * v1.y; acc[6] += w * v1.z; acc[7] += w * v1.w;
        }
        float bj = Wl_b[jc];
        #pragma unroll
        for (int q = 0; q < 8; q++) swh[jc * 17 + half * 8 + q] = acc[q] + bj;
    }
    __syncthreads();

    // Phase 1: scores — warp w owns t = w, w+8, ..., 4-row chains for MLP
    {
        const int warp = tid >> 5, lane = tid & 31;
        const float vb = Vb[0];
        for (int t = warp; t < TT; t += 8) {
            const float* uo = Uo + ((size_t)t * BB + b0) * HH;
            #pragma unroll
            for (int r4 = 0; r4 < 16; r4 += 4) {
                float a0 = 0.f, a1 = 0.f, a2 = 0.f, a3 = 0.f;
                #pragma unroll
                for (int m = 0; m < 4; m++) {
                    int c = lane + 32 * m;
                    if (c < HH) {
                        float vv = V[c];
                        float w0 = swh[c * 17 + r4 + 0];
                        float w1 = swh[c * 17 + r4 + 1];
                        float w2 = swh[c * 17 + r4 + 2];
                        float w3 = swh[c * 17 + r4 + 3];
                        a0 += tanhp(uo[(size_t)(r4 + 0) * HH + c] + w0) * vv;
                        a1 += tanhp(uo[(size_t)(r4 + 1) * HH + c] + w1) * vv;
                        a2 += tanhp(uo[(size_t)(r4 + 2) * HH + c] + w2) * vv;
                        a3 += tanhp(uo[(size_t)(r4 + 3) * HH + c] + w3) * vv;
                    }
                }
                #pragma unroll
                for (int off = 16; off; off >>= 1) {
                    a0 += __shfl_down_sync(0xffffffffu, a0, off);
                    a1 += __shfl_down_sync(0xffffffffu, a1, off);
                    a2 += __shfl_down_sync(0xffffffffu, a2, off);
                    a3 += __shfl_down_sync(0xffffffffu, a3, off);
                }
                if (lane == 0) {
                    sc[t * 17 + r4 + 0] = a0 + vb;
                    sc[t * 17 + r4 + 1] = a1 + vb;
                    sc[t * 17 + r4 + 2] = a2 + vb;
                    sc[t * 17 + r4 + 3] = a3 + vb;
                }
            }
        }
    }
    __syncthreads();

    // Phase 2: softmax over t per row; build x head
    if (tid < 16) {
        int r = tid;
        float mx = -1e30f;
        for (int t = 0; t < TT; t++) mx = fmaxf(mx, sc[t * 17 + r]);
        float sum = 0.f;
        for (int t = 0; t < TT; t++) {
            float e = ex2f((sc[t * 17 + r] - mx) * LOG2E_);
            sc[t * 17 + r] = e;
            sum += e;
        }
        float inv = rcpf(sum);
        for (int t = 0; t < TT; t++) sc[t * 17 + r] *= inv;
        float prev = (step == 0) ? enc_data[((size_t)(TT - 1) * BB + b0 + r) * ENC_]
                                 : outbuf[(size_t)(step - 1) * BB + b0 + r];
        x[(size_t)(b0 + r) * DIN_] = prev;
    } else if (tid < 16 + 240) {
        int i2 = tid - 16;
        int r = i2 / DEC_, c = i2 % DEC_;
        x[(size_t)(b0 + r) * DIN_ + 1 + c] = dec_data[((size_t)step * BB + b0 + r) * DEC_ + c];
    }
    __syncthreads();

    // Phase 3: attn context
    if (jc < HH) {
        float acc[8];
        #pragma unroll
        for (int q = 0; q < 8; q++) acc[q] = 0.f;
        for (int t = 0; t < TT; t++) {
            const float* eo = enc_out + ((size_t)t * BB + b0 + half * 8) * HH + jc;
            #pragma unroll
            for (int q = 0; q < 8; q++) {
                float a = sc[t * 17 + half * 8 + q];
                acc[q] += a * eo[(size_t)q * HH];
            }
        }
        #pragma unroll
        for (int q = 0; q < 8; q++)
            x[(size_t)(b0 + half * 8 + q) * DIN_ + 1 + DEC_ + jc] = acc[q];
    }
}

// ---------------- host side ----------------
extern "C" void kernel_launch(void* const* d_in, const int* in_sizes, int n_in,
                              void* d_out, int out_size) {
    const float* ann      = (const float*)d_in[0];
    const float* enc_data = (const float*)d_in[1];
    const float* dec_data = (const float*)d_in[2];
    const float* s2h_W1   = (const float*)d_in[3];
    const float* s2h_b1   = (const float*)d_in[4];
    const float* s2h_W2   = (const float*)d_in[5];
    const float* s2h_b2   = (const float*)d_in[6];
    const float* enc_Wih  = (const float*)d_in[7];
    const float* enc_Whh  = (const float*)d_in[8];
    const float* enc_bih  = (const float*)d_in[9];
    const float* enc_bhh  = (const float*)d_in[10];
    const float* dec_Wih  = (const float*)d_in[11];
    const float* dec_Whh  = (const float*)d_in[12];
    const float* dec_bih  = (const float*)d_in[13];
    const float* dec_bhh  = (const float*)d_in[14];
    const float* U_W      = (const float*)d_in[15];
    const float* U_b      = (const float*)d_in[16];
    const float* Wl_W     = (const float*)d_in[17];
    const float* Wl_b     = (const float*)d_in[18];
    const float* V_W      = (const float*)d_in[19];
    const float* V_b      = (const float*)d_in[20];
    const float* h2o_W    = (const float*)d_in[21];
    const float* h2o_b    = (const float*)d_in[22];
    float* outp = (float*)d_out;

    float *h0, *h1, *enc_out, *Uo, *x, *Wenc, *Wdec, *UWTp, *WlT;
    cudaGetSymbolAddress((void**)&h0, g_h0);
    cudaGetSymbolAddress((void**)&h1, g_h1);
    cudaGetSymbolAddress((void**)&enc_out, g_enc_out);
    cudaGetSymbolAddress((void**)&Uo, g_Uo);
    cudaGetSymbolAddress((void**)&x, g_x);
    cudaGetSymbolAddress((void**)&Wenc, g_Wenc);
    cudaGetSymbolAddress((void**)&Wdec, g_Wdec);
    cudaGetSymbolAddress((void**)&UWTp, g_UWTp);
    cudaGetSymbolAddress((void**)&WlT, g_WlT);

    const size_t sm_enc = (size_t)(KP_E * 20 + GG * 17 + HH * 17 + 16) * 4;
    const size_t sm_dec = (size_t)(KP_D * 20 + GG * 17 + HH * 17 + 16) * 4;
    const size_t sm_uo  = (size_t)(HH * 128 + HH * 36) * 4;
    cudaFuncSetAttribute((const void*)gru3_kernel<ENC_, XDP_E, KP_E, false>,
                         cudaFuncAttributeMaxDynamicSharedMemorySize, (int)sm_enc);
    cudaFuncSetAttribute((const void*)gru3_kernel<DIN_, XDP_D, KP_D, true>,
                         cudaFuncAttributeMaxDynamicSharedMemorySize, (int)sm_dec);
    cudaFuncSetAttribute((const void*)uo_kernel,
                         cudaFuncAttributeMaxDynamicSharedMemorySize, (int)sm_uo);

    const int total_w = KP_E * 384 + KP_D * 384 + HH * 128 + HH * HH;
    prep_weights<<<(total_w + 255) / 256, 256>>>(enc_Wih, enc_Whh, dec_Wih, dec_Whh, U_W, Wl_W);

    s2h_kernel<<<BB, 128>>>(ann, s2h_W1, s2h_b1, s2h_W2, s2h_b2, h0);

    // encoder: hidden for step t written directly into enc_out[t]
    for (int t = 0; t < TT; t++) {
        const float* hin = (t == 0) ? h0 : enc_out + (size_t)(t - 1) * BB * HH;
        gru3_kernel<ENC_, XDP_E, KP_E, false><<<BB / 16, 384, sm_enc>>>(
            hin, enc_data + (size_t)t * BB * ENC_, Wenc, enc_bih, enc_bhh,
            enc_out + (size_t)t * BB * HH, nullptr, nullptr, nullptr);
    }

    uo_kernel<<<(TT * BB) / 32, 256, sm_uo>>>(enc_out, UWTp, U_b, Uo);

    const float* enc_last = enc_out + (size_t)(TT - 1) * BB * HH;
    for (int s = 0; s < NSTEPS; s++) {
        const float* hcur = (s == 0) ? enc_last : ((s & 1) ? h0 : h1);
        float* hnext      = (s & 1) ? h1 : h0;
        attn_fused_kernel<<<BB / 16, 256>>>(hcur, Uo, enc_out, WlT, Wl_b, V_W, V_b,
                                            enc_data, dec_data, outp, x, s);
        gru3_kernel<DIN_, XDP_D, KP_D, true><<<BB / 16, 384, sm_dec>>>(
            hcur, x, Wdec, dec_bih, dec_bhh, hnext, h2o_W, h2o_b, outp + (size_t)s * BB);
    }
}

// round 5
// speedup vs baseline: 1.2823x; 1.1070x over previous
#include <cuda_runtime.h>
#include <math.h>

#define BB     4096
#define TT     56
#define NSTEPS 28
#define HH     126
#define GG     378
#define ANN_   30
#define ENC_   20
#define DEC_   15

#define HS     128      // padded hidden stride
#define ROWS   14
#define NBLK   ((BB + ROWS - 1) / ROWS)   // 293

// ---------------- scratch (device globals; no allocations) ----------------
__device__ float g_h0[BB * HS];
__device__ float g_h1[BB * HS];
__device__ float g_enc_out[TT * BB * HS];
__device__ float g_Uo[TT * BB * HS];
__device__ float g_x[BB * HS];                 // [attn(126), prev, pad]
__device__ float g_giE[(size_t)TT * BB * 384]; // enc input-gates, padded 384
__device__ float g_giD[(size_t)NSTEPS * BB * 384];
__device__ float g_Wenc[128 * 384];            // h-part weights
__device__ float g_Wdec[256 * 384];            // [attn,prev,pad | h,pad]
__device__ float g_WgiE[ENC_ * 384];
__device__ float g_WgiD[DEC_ * 384];
__device__ float g_UWTp[HH * HS];
__device__ float g_WlTp[HH * HS];
__device__ float g_Ubp[HS];
__device__ float g_Wlbp[HS];
__device__ float g_Vp[HS];

// ---------------- fast transcendentals ----------------
__device__ __forceinline__ float ex2f(float x) { float y; asm("ex2.approx.f32 %0, %1;" : "=f"(y) : "f"(x)); return y; }
__device__ __forceinline__ float rcpf(float x) { float y; asm("rcp.approx.f32 %0, %1;" : "=f"(y) : "f"(x)); return y; }
__device__ __forceinline__ float tanha(float x) { float y; asm("tanh.approx.f32 %0, %1;" : "=f"(y) : "f"(x)); return y; }
#define LOG2E_ 1.4426950408889634f
// accurate-ish forms for GRU gates (error ~1e-6)
__device__ __forceinline__ float sigf(float v)  { return rcpf(1.0f + ex2f(-v * LOG2E_)); }
__device__ __forceinline__ float tanhp(float v) { return 2.0f * rcpf(1.0f + ex2f(-2.0f * v * LOG2E_)) - 1.0f; }

// ---------------- weight prep ----------------
__global__ void prep_weights(const float* __restrict__ eWih, const float* __restrict__ eWhh,
                             const float* __restrict__ dWih, const float* __restrict__ dWhh,
                             const float* __restrict__ U,    const float* __restrict__ Ub,
                             const float* __restrict__ Wl,   const float* __restrict__ Wlb,
                             const float* __restrict__ V) {
    int i = blockIdx.x * 256 + threadIdx.x;
    const int Nwe = 128 * 384, Nwd = 256 * 384, Nge = ENC_ * 384, Ngd = DEC_ * 384;
    const int Nuw = HH * HS;
    if (i < Nwe) {
        int k = i / 384, j = i % 384;
        g_Wenc[i] = (j < GG && k < HH) ? eWhh[j * HH + k] : 0.0f;
        return;
    }
    i -= Nwe;
    if (i < Nwd) {
        int k = i / 384, j = i % 384;
        float v = 0.0f;
        if (j < GG) {
            if (k < 126) v = dWih[j * 142 + 16 + k];        // attn cols
            else if (k == 126) v = dWih[j * 142 + 0];        // prev col
            else if (k >= 128 && k < 254) v = dWhh[j * HH + (k - 128)];
        }
        g_Wdec[i] = v; return;
    }
    i -= Nwd;
    if (i < Nge) {
        int k = i / 384, j = i % 384;
        g_WgiE[i] = (j < GG) ? eWih[j * ENC_ + k] : 0.0f;
        return;
    }
    i -= Nge;
    if (i < Ngd) {
        int k = i / 384, j = i % 384;
        g_WgiD[i] = (j < GG) ? dWih[j * 142 + 1 + k] : 0.0f;
        return;
    }
    i -= Ngd;
    if (i < Nuw) { int k = i / HS, j = i % HS; g_UWTp[i] = (j < HH) ? U[j * HH + k] : 0.0f; return; }
    i -= Nuw;
    if (i < Nuw) { int k = i / HS, j = i % HS; g_WlTp[i] = (j < HH) ? Wl[j * HH + k] : 0.0f; return; }
    i -= Nuw;
    if (i < HS) { g_Ubp[i] = (i < HH) ? Ub[i] : 0.0f; return; }
    i -= HS;
    if (i < HS) { g_Wlbp[i] = (i < HH) ? Wlb[i] : 0.0f; return; }
    i -= HS;
    if (i < HS) { g_Vp[i] = (i < HH) ? V[i] : 0.0f; }
}

// ---------------- s2h MLP ----------------
__global__ void s2h_kernel(const float* __restrict__ ann,
                           const float* __restrict__ W1, const float* __restrict__ b1,
                           const float* __restrict__ W2, const float* __restrict__ b2,
                           float* __restrict__ h) {
    __shared__ float a[ANN_];
    __shared__ float mid[96];
    int b = blockIdx.x;
    int tid = threadIdx.x;
    if (tid < ANN_) a[tid] = ann[b * ANN_ + tid];
    __syncthreads();
    if (tid < 96) {
        float acc = b1[tid];
        #pragma unroll
        for (int k = 0; k < ANN_; k++) acc += W1[tid * ANN_ + k] * a[k];
        mid[tid] = fmaxf(acc, 0.0f);
    }
    __syncthreads();
    if (tid < HH) {
        float acc = b2[tid];
        #pragma unroll 4
        for (int k = 0; k < 96; k++) acc += W2[tid * 96 + k] * mid[k];
        h[(size_t)b * HS + tid] = acc;
    }
}

// ---------------- gi GEMM: gi[row][384] = in[row][KD] @ Wg[KD][384] ----------------
template <int KD>
__global__ __launch_bounds__(384) void gi_kernel(const float* __restrict__ in,
                                                 const float* __restrict__ Wg,
                                                 float* __restrict__ gi) {
    __shared__ float s_w[KD * 384];
    __shared__ float s_in[KD * 16];
    const int tid = threadIdx.x;
    const int b0 = blockIdx.x * 16;
    for (int i = tid; i < KD * 96; i += 384)
        reinterpret_cast<float4*>(s_w)[i] = reinterpret_cast<const float4*>(Wg)[i];
    for (int i = tid; i < KD * 16; i += 384) {
        int r = i / KD, k = i % KD;
        s_in[k * 16 + r] = in[(size_t)(b0 + r) * KD + k];
    }
    __syncthreads();
    float acc[16];
    #pragma unroll
    for (int r = 0; r < 16; r++) acc[r] = 0.0f;
    #pragma unroll 4
    for (int k = 0; k < KD; k++) {
        float w = s_w[k * 384 + tid];
        const float4* sp = reinterpret_cast<const float4*>(s_in + k * 16);
        float4 v0 = sp[0], v1 = sp[1], v2 = sp[2], v3 = sp[3];
        acc[0]  += w * v0.x; acc[1]  += w * v0.y; acc[2]  += w * v0.z; acc[3]  += w * v0.w;
        acc[4]  += w * v1.x; acc[5]  += w * v1.y; acc[6]  += w * v1.z; acc[7]  += w * v1.w;
        acc[8]  += w * v2.x; acc[9]  += w * v2.y; acc[10] += w * v2.z; acc[11] += w * v2.w;
        acc[12] += w * v3.x; acc[13] += w * v3.y; acc[14] += w * v3.z; acc[15] += w * v3.w;
    }
    if (tid < GG) {
        #pragma unroll
        for (int r = 0; r < 16; r++) gi[(size_t)(b0 + r) * 384 + tid] = acc[r];
    }
}

// ---------------- GRU recurrent step ----------------
template <int KP, bool HAS_X, bool IS_DEC>
__global__ __launch_bounds__(384, 2) void gruK(
        const float* __restrict__ h_in,   // stride HS
        const float* __restrict__ x,      // stride HS (HAS_X)
        const float* __restrict__ W,      // [KP][384]
        const float* __restrict__ gi,     // [row][384]
        const float* __restrict__ bih, const float* __restrict__ bhh,
        float* __restrict__ h_out,
        const float* __restrict__ h2oW, const float* __restrict__ h2ob,
        float* __restrict__ out) {
    constexpr int NC = KP / 8;
    constexpr int XDP = HAS_X ? 128 : 0;
    extern __shared__ float sm[];
    float* s_in   = sm;                       // KP*16
    float* pool   = sm + KP * 16;             // weights db / preacts
    float* s_preA = pool;                     // 378*15
    float* s_preB = pool + GG * 15;           // 126*15
    float* s_out  = pool + GG * 15 + HH * 15; // 14

    const int tid = threadIdx.x;
    const int b0 = blockIdx.x * ROWS;
    const int nrow = min(ROWS, BB - b0);

    if (IS_DEC && tid < ROWS) s_out[tid] = 0.0f;

    if (HAS_X) {
        for (int i = tid; i < 127 * ROWS; i += 384) {
            int r = i / 127, k = i % 127;
            s_in[k * 16 + r] = (r < nrow) ? x[(size_t)(b0 + r) * HS + k] : 0.0f;
        }
        if (tid < ROWS) s_in[127 * 16 + tid] = 0.0f;
    }
    for (int i = tid; i < HH * ROWS; i += 384) {
        int r = i / HH, k = i % HH;
        s_in[(XDP + k) * 16 + r] = (r < nrow) ? h_in[(size_t)(b0 + r) * HS + k] : 0.0f;
    }
    if (tid < 2 * ROWS) {
        int k = tid / ROWS, r = tid % ROWS;
        s_in[(XDP + HH + k) * 16 + r] = 0.0f;
    }
    {
        const float4* src = reinterpret_cast<const float4*>(W);
        float4* dst = reinterpret_cast<float4*>(pool);
        dst[tid] = src[tid];
        dst[tid + 384] = src[tid + 384];
    }
    __syncthreads();

    float acc[ROWS], accx[ROWS];
    #pragma unroll
    for (int r = 0; r < ROWS; r++) { acc[r] = 0.0f; accx[r] = 0.0f; }

    for (int c = 0; c < NC; c++) {
        const int cur = c & 1;
        if (c + 1 < NC) {
            const float4* src = reinterpret_cast<const float4*>(W + (size_t)(c + 1) * 8 * 384);
            float4* dst = reinterpret_cast<float4*>(pool + (1 - cur) * 3072);
            dst[tid] = src[tid];
            dst[tid + 384] = src[tid + 384];
        }
        const float* wp = pool + cur * 3072 + tid;
        const float* ip = s_in + c * 8 * 16;
        #pragma unroll
        for (int kk = 0; kk < 8; kk++) {
            float w = wp[kk * 384];
            const float* sp = ip + kk * 16;
            float4 v0 = *reinterpret_cast<const float4*>(sp);
            float4 v1 = *reinterpret_cast<const float4*>(sp + 4);
            float4 v2 = *reinterpret_cast<const float4*>(sp + 8);
            float2 v3 = *reinterpret_cast<const float2*>(sp + 12);
            acc[0]  += w * v0.x; acc[1]  += w * v0.y; acc[2]  += w * v0.z; acc[3]  += w * v0.w;
            acc[4]  += w * v1.x; acc[5]  += w * v1.y; acc[6]  += w * v1.z; acc[7]  += w * v1.w;
            acc[8]  += w * v2.x; acc[9]  += w * v2.y; acc[10] += w * v2.z; acc[11] += w * v2.w;
            acc[12] += w * v3.x; acc[13] += w * v3.y;
        }
        if (HAS_X && c == 15) {
            #pragma unroll
            for (int r = 0; r < ROWS; r++) accx[r] = acc[r];
        }
        __syncthreads();
    }

    if (tid < GG) {
        #pragma unroll
        for (int r = 0; r < ROWS; r++) s_preA[tid * 15 + r] = acc[r];
    }
    if (HAS_X && tid >= 2 * HH && tid < GG) {
        #pragma unroll
        for (int r = 0; r < ROWS; r++) s_preB[(tid - 2 * HH) * 15 + r] = accx[r];
    }
    __syncthreads();

    for (int i = tid; i < ROWS * 128; i += 384) {
        int r = i >> 7;
        int j = i & 127;
        if (r >= nrow) continue;
        if (j < HH) {
            const float* gir = gi + (size_t)(b0 + r) * 384;
            float pr = s_preA[j * 15 + r]        + gir[j]      + bih[j]      + bhh[j];
            float pz = s_preA[(HH + j) * 15 + r] + gir[HH + j] + bih[HH + j] + bhh[HH + j];
            float nx, nh;
            if (HAS_X) {
                float sx = s_preB[j * 15 + r];
                nx = sx + gir[2 * HH + j] + bih[2 * HH + j];
                nh = s_preA[(2 * HH + j) * 15 + r] - sx + bhh[2 * HH + j];
            } else {
                nx = gir[2 * HH + j] + bih[2 * HH + j];
                nh = s_preA[(2 * HH + j) * 15 + r] + bhh[2 * HH + j];
            }
            float rg = sigf(pr);
            float zg = sigf(pz);
            float nn = tanhp(nx + rg * nh);
            float hv = s_in[(XDP + j) * 16 + r];
            float hnew = (1.0f - zg) * nn + zg * hv;
            h_out[(size_t)(b0 + r) * HS + j] = hnew;
            if (IS_DEC) atomicAdd(&s_out[r], hnew * h2oW[j]);
        } else if (!IS_DEC) {
            h_out[(size_t)(b0 + r) * HS + j] = 0.0f;   // zero pads of enc_out
        }
    }
    if (IS_DEC) {
        __syncthreads();
        if (tid < nrow) out[b0 + tid] = s_out[tid] + h2ob[0];
    }
}

// ---------------- Uo = enc_out @ U^T + b, weights smem-resident ----------------
__global__ __launch_bounds__(256, 2) void uo_kernel(const float* __restrict__ in,
                                                    const float* __restrict__ Wp,
                                                    const float* __restrict__ biasp,
                                                    float* __restrict__ out) {
    constexpr int PIN = 36;
    extern __shared__ float sm[];
    float* s_w  = sm;              // 126*128
    float* s_in = sm + HH * HS;    // 126*36
    const int tid = threadIdx.x;
    const int b0 = blockIdx.x * 32;

    {
        const float4* src = reinterpret_cast<const float4*>(Wp);
        float4* dst = reinterpret_cast<float4*>(s_w);
        for (int v = tid; v < HH * HS / 4; v += 256) dst[v] = src[v];
    }
    for (int idx = tid; idx < HH * 32; idx += 256) {
        int r = idx / HH, k = idx % HH;
        s_in[k * PIN + r] = in[(size_t)(b0 + r) * HS + k];
    }
    __syncthreads();

    const int j = tid & 127;
    const int half = tid >> 7;
    float acc[16];
    #pragma unroll
    for (int r = 0; r < 16; r++) acc[r] = 0.0f;
    #pragma unroll 2
    for (int k = 0; k < HH; k++) {
        float w = s_w[k * HS + j];
        const float4* sp = reinterpret_cast<const float4*>(s_in + k * PIN + half * 16);
        float4 v0 = sp[0], v1 = sp[1], v2 = sp[2], v3 = sp[3];
        acc[0]  += w * v0.x; acc[1]  += w * v0.y; acc[2]  += w * v0.z; acc[3]  += w * v0.w;
        acc[4]  += w * v1.x; acc[5]  += w * v1.y; acc[6]  += w * v1.z; acc[7]  += w * v1.w;
        acc[8]  += w * v2.x; acc[9]  += w * v2.y; acc[10] += w * v2.z; acc[11] += w * v2.w;
        acc[12] += w * v3.x; acc[13] += w * v3.y; acc[14] += w * v3.z; acc[15] += w * v3.w;
    }
    float bj = biasp[j];
    #pragma unroll
    for (int r = 0; r < 16; r++)
        out[(size_t)(b0 + half * 16 + r) * HS + j] = acc[r] + bj;
}

// ---------------- fused decoder attention (16 rows/block, 256 threads) ----------------
__global__ __launch_bounds__(256) void attn2_kernel(
        const float* __restrict__ h,
        const float* __restrict__ Uo, const float* __restrict__ enc_out,
        const float* __restrict__ WlTp, const float* __restrict__ Wlbp,
        const float* __restrict__ Vp, const float* __restrict__ Vb,
        const float* __restrict__ enc_data,
        const float* __restrict__ outbuf,
        float* __restrict__ x, int step) {
    __shared__ float sh[HH * 16];      // h tile k-major
    __shared__ float swh[16 * HS];     // Wh row-major
    __shared__ float sc[TT * 17];      // scores -> alpha

    const int tid = threadIdx.x;
    const int b0 = blockIdx.x * 16;
    const int jc = tid & 127;
    const int half = tid >> 7;
    const int warp = tid >> 5, lane = tid & 31;

    for (int idx = tid; idx < HH * 16; idx += 256) {
        int r = idx / HH, k = idx % HH;
        sh[k * 16 + r] = h[(size_t)(b0 + r) * HS + k];
    }
    __syncthreads();

    // Phase 0: Wh = h @ Wl^T + b (cols jc, 8 rows per thread)
    {
        float acc[8];
        #pragma unroll
        for (int q = 0; q < 8; q++) acc[q] = 0.f;
        #pragma unroll 2
        for (int k = 0; k < HH; k++) {
            float w = WlTp[k * HS + jc];
            const float4* sp = reinterpret_cast<const float4*>(sh + k * 16) + half * 2;
            float4 v0 = sp[0], v1 = sp[1];
            acc[0] += w * v0.x; acc[1] += w * v0.y; acc[2] += w * v0.z; acc[3] += w * v0.w;
            acc[4] += w * v1.x; acc[5] += w * v1.y; acc[6] += w * v1.z; acc[7] += w * v1.w;
        }
        float bj = Wlbp[jc];
        #pragma unroll
        for (int q = 0; q < 8; q++) swh[(half * 8 + q) * HS + jc] = acc[q] + bj;
    }
    __syncthreads();

    // Phase 1: scores, warp w owns rows 2w, 2w+1; float4 streaming over Uo
    {
        const int r0 = 2 * warp, r1 = r0 + 1;
        float4 w0 = *reinterpret_cast<const float4*>(&swh[r0 * HS + lane * 4]);
        float4 w1 = *reinterpret_cast<const float4*>(&swh[r1 * HS + lane * 4]);
        float4 vv = *reinterpret_cast<const float4*>(&Vp[lane * 4]);
        float vb = Vb[0];
        for (int t = 0; t < TT; t += 2) {
            float4 u0 = *(reinterpret_cast<const float4*>(Uo + ((size_t)t * BB + b0 + r0) * HS) + lane);
            float4 u1 = *(reinterpret_cast<const float4*>(Uo + ((size_t)t * BB + b0 + r1) * HS) + lane);
            float4 u2 = *(reinterpret_cast<const float4*>(Uo + ((size_t)(t + 1) * BB + b0 + r0) * HS) + lane);
            float4 u3 = *(reinterpret_cast<const float4*>(Uo + ((size_t)(t + 1) * BB + b0 + r1) * HS) + lane);
            float a0 = tanha(u0.x + w0.x) * vv.x + tanha(u0.y + w0.y) * vv.y
                     + tanha(u0.z + w0.z) * vv.z + tanha(u0.w + w0.w) * vv.w;
            float a1 = tanha(u1.x + w1.x) * vv.x + tanha(u1.y + w1.y) * vv.y
                     + tanha(u1.z + w1.z) * vv.z + tanha(u1.w + w1.w) * vv.w;
            float a2 = tanha(u2.x + w0.x) * vv.x + tanha(u2.y + w0.y) * vv.y
                     + tanha(u2.z + w0.z) * vv.z + tanha(u2.w + w0.w) * vv.w;
            float a3 = tanha(u3.x + w1.x) * vv.x + tanha(u3.y + w1.y) * vv.y
                     + tanha(u3.z + w1.z) * vv.z + tanha(u3.w + w1.w) * vv.w;
            #pragma unroll
            for (int off = 16; off; off >>= 1) {
                a0 += __shfl_down_sync(0xffffffffu, a0, off);
                a1 += __shfl_down_sync(0xffffffffu, a1, off);
                a2 += __shfl_down_sync(0xffffffffu, a2, off);
                a3 += __shfl_down_sync(0xffffffffu, a3, off);
            }
            if (lane == 0) {
                sc[t * 17 + r0] = a0 + vb;
                sc[t * 17 + r1] = a1 + vb;
                sc[(t + 1) * 17 + r0] = a2 + vb;
                sc[(t + 1) * 17 + r1] = a3 + vb;
            }
        }
    }
    __syncthreads();

    // Phase 2: softmax over t per row
    if (tid < 16) {
        int r = tid;
        float mx = -1e30f;
        for (int t = 0; t < TT; t++) mx = fmaxf(mx, sc[t * 17 + r]);
        float sum = 0.f;
        for (int t = 0; t < TT; t++) {
            float e = ex2f((sc[t * 17 + r] - mx) * LOG2E_);
            sc[t * 17 + r] = e;
            sum += e;
        }
        float inv = rcpf(sum);
        for (int t = 0; t < TT; t++) sc[t * 17 + r] *= inv;
    }
    __syncthreads();

    // Phase 3: attn context, float4 streaming over enc_out
    {
        const int r0 = 2 * warp, r1 = r0 + 1;
        float4 acc0 = {0.f, 0.f, 0.f, 0.f}, acc1 = {0.f, 0.f, 0.f, 0.f};
        for (int t = 0; t < TT; t++) {
            float al0 = sc[t * 17 + r0], al1 = sc[t * 17 + r1];
            float4 e0 = *(reinterpret_cast<const float4*>(enc_out + ((size_t)t * BB + b0 + r0) * HS) + lane);
            float4 e1 = *(reinterpret_cast<const float4*>(enc_out + ((size_t)t * BB + b0 + r1) * HS) + lane);
            acc0.x += al0 * e0.x; acc0.y += al0 * e0.y; acc0.z += al0 * e0.z; acc0.w += al0 * e0.w;
            acc1.x += al1 * e1.x; acc1.y += al1 * e1.y; acc1.z += al1 * e1.z; acc1.w += al1 * e1.w;
        }
        *(reinterpret_cast<float4*>(x + (size_t)(b0 + r0) * HS) + lane) = acc0;
        *(reinterpret_cast<float4*>(x + (size_t)(b0 + r1) * HS) + lane) = acc1;
    }
    __syncthreads();
    if (tid < 16) {
        float prev = (step == 0) ? enc_data[((size_t)(TT - 1) * BB + b0 + tid) * ENC_]
                                 : outbuf[(size_t)(step - 1) * BB + b0 + tid];
        x[(size_t)(b0 + tid) * HS + 126] = prev;
    }
}

// ---------------- host side ----------------
extern "C" void kernel_launch(void* const* d_in, const int* in_sizes, int n_in,
                              void* d_out, int out_size) {
    const float* ann      = (const float*)d_in[0];
    const float* enc_data = (const float*)d_in[1];
    const float* dec_data = (const float*)d_in[2];
    const float* s2h_W1   = (const float*)d_in[3];
    const float* s2h_b1   = (const float*)d_in[4];
    const float* s2h_W2   = (const float*)d_in[5];
    const float* s2h_b2   = (const float*)d_in[6];
    const float* enc_Wih  = (const float*)d_in[7];
    const float* enc_Whh  = (const float*)d_in[8];
    const float* enc_bih  = (const float*)d_in[9];
    const float* enc_bhh  = (const float*)d_in[10];
    const float* dec_Wih  = (const float*)d_in[11];
    const float* dec_Whh  = (const float*)d_in[12];
    const float* dec_bih  = (const float*)d_in[13];
    const float* dec_bhh  = (const float*)d_in[14];
    const float* U_W      = (const float*)d_in[15];
    const float* U_b      = (const float*)d_in[16];
    const float* Wl_W     = (const float*)d_in[17];
    const float* Wl_b     = (const float*)d_in[18];
    const float* V_W      = (const float*)d_in[19];
    const float* V_b      = (const float*)d_in[20];
    const float* h2o_W    = (const float*)d_in[21];
    const float* h2o_b    = (const float*)d_in[22];
    float* outp = (float*)d_out;

    float *h0, *h1, *enc_out, *Uo, *x, *giE, *giD;
    float *Wenc, *Wdec, *WgiE, *WgiD, *UWTp, *WlTp, *Ubp, *Wlbp, *Vp;
    cudaGetSymbolAddress((void**)&h0, g_h0);
    cudaGetSymbolAddress((void**)&h1, g_h1);
    cudaGetSymbolAddress((void**)&enc_out, g_enc_out);
    cudaGetSymbolAddress((void**)&Uo, g_Uo);
    cudaGetSymbolAddress((void**)&x, g_x);
    cudaGetSymbolAddress((void**)&giE, g_giE);
    cudaGetSymbolAddress((void**)&giD, g_giD);
    cudaGetSymbolAddress((void**)&Wenc, g_Wenc);
    cudaGetSymbolAddress((void**)&Wdec, g_Wdec);
    cudaGetSymbolAddress((void**)&WgiE, g_WgiE);
    cudaGetSymbolAddress((void**)&WgiD, g_WgiD);
    cudaGetSymbolAddress((void**)&UWTp, g_UWTp);
    cudaGetSymbolAddress((void**)&WlTp, g_WlTp);
    cudaGetSymbolAddress((void**)&Ubp, g_Ubp);
    cudaGetSymbolAddress((void**)&Wlbp, g_Wlbp);
    cudaGetSymbolAddress((void**)&Vp, g_Vp);

    const size_t sm_enc = (size_t)(128 * 16 + 2 * 3072) * 4;                    // 32768
    const size_t sm_dec = (size_t)(256 * 16 + GG * 15 + HH * 15 + 16) * 4;      // ~46.7KB
    const size_t sm_uo  = (size_t)(HH * HS + HH * 36) * 4;                      // ~82.7KB
    cudaFuncSetAttribute((const void*)gruK<128, false, false>,
                         cudaFuncAttributeMaxDynamicSharedMemorySize, (int)sm_enc);
    cudaFuncSetAttribute((const void*)gruK<256, true, true>,
                         cudaFuncAttributeMaxDynamicSharedMemorySize, (int)sm_dec);
    cudaFuncSetAttribute((const void*)uo_kernel,
                         cudaFuncAttributeMaxDynamicSharedMemorySize, (int)sm_uo);

    const int total_w = 128 * 384 + 256 * 384 + ENC_ * 384 + DEC_ * 384
                      + 2 * HH * HS + 3 * HS;
    prep_weights<<<(total_w + 255) / 256, 256>>>(enc_Wih, enc_Whh, dec_Wih, dec_Whh,
                                                 U_W, U_b, Wl_W, Wl_b, V_W);

    s2h_kernel<<<BB, 128>>>(ann, s2h_W1, s2h_b1, s2h_W2, s2h_b2, h0);

    // input-side GEMMs hoisted out of the recurrences
    gi_kernel<ENC_><<<TT * BB / 16, 384>>>(enc_data, WgiE, giE);
    gi_kernel<DEC_><<<NSTEPS * BB / 16, 384>>>(dec_data, WgiD, giD);

    // encoder scan: hidden t written into enc_out[t]
    for (int t = 0; t < TT; t++) {
        const float* hin = (t == 0) ? h0 : enc_out + (size_t)(t - 1) * BB * HS;
        gruK<128, false, false><<<NBLK, 384, sm_enc>>>(
            hin, nullptr, Wenc, giE + (size_t)t * BB * 384, enc_bih, enc_bhh,
            enc_out + (size_t)t * BB * HS, nullptr, nullptr, nullptr);
    }

    uo_kernel<<<TT * BB / 32, 256, sm_uo>>>(enc_out, UWTp, Ubp, Uo);

    const float* enc_last = enc_out + (size_t)(TT - 1) * BB * HS;
    for (int s = 0; s < NSTEPS; s++) {
        const float* hcur = (s == 0) ? enc_last : ((s & 1) ? h0 : h1);
        float* hnext      = (s & 1) ? h1 : h0;
        attn2_kernel<<<BB / 16, 256>>>(hcur, Uo, enc_out, WlTp, Wlbp, Vp, V_b,
                                       enc_data, outp, x, s);
        gruK<256, true, true><<<NBLK, 384, sm_dec>>>(
            hcur, x, Wdec, giD + (size_t)s * BB * 384, dec_bih, dec_bhh,
            hnext, h2o_W, h2o_b, outp + (size_t)s * BB);
    }
}

// round 7
// speedup vs baseline: 1.4291x; 1.1145x over previous
#include <cuda_runtime.h>
#include <cstdint>
#include <math.h>

#define BB     4096
#define TT     56
#define NSTEPS 28
#define HH     126
#define GG     378
#define ANN_   30
#define ENC_   20
#define DEC_   15

#define HS     128      // padded hidden stride
#define ROWS   14
#define NBLK   ((BB + ROWS - 1) / ROWS)   // 293
#define PIN    20       // s_in pitch

// ---------------- scratch (device globals; no allocations) ----------------
__device__ float g_h0[BB * HS];
__device__ float g_h1[BB * HS];
__device__ float g_enc_out[TT * BB * HS];
__device__ float g_Uo[TT * BB * HS];
__device__ float g_Wh[BB * HS];
__device__ float g_scores[TT * BB];
__device__ float g_x[BB * HS];                 // [attn(126), prev, pad]
__device__ float g_giE[(size_t)TT * BB * 384];
__device__ float g_giD[(size_t)NSTEPS * BB * 384];
__device__ float g_Wenc[128 * 384];
__device__ float g_Wdec[256 * 384];
__device__ float g_WgiE[ENC_ * 384];
__device__ float g_WgiD[DEC_ * 384];
__device__ float g_UWTp[HH * HS];
__device__ float g_WlTp[HH * HS];
__device__ float g_Ubp[HS];
__device__ float g_Wlbp[HS];
__device__ float g_Vp[HS];

// ---------------- fast transcendentals ----------------
__device__ __forceinline__ float ex2f(float x) { float y; asm("ex2.approx.f32 %0, %1;" : "=f"(y) : "f"(x)); return y; }
__device__ __forceinline__ float rcpf(float x) { float y; asm("rcp.approx.f32 %0, %1;" : "=f"(y) : "f"(x)); return y; }
__device__ __forceinline__ float tanha(float x) { float y; asm("tanh.approx.f32 %0, %1;" : "=f"(y) : "f"(x)); return y; }
#define LOG2E_ 1.4426950408889634f
__device__ __forceinline__ float sigf(float v)  { return rcpf(1.0f + ex2f(-v * LOG2E_)); }
__device__ __forceinline__ float tanhp(float v) { return 2.0f * rcpf(1.0f + ex2f(-2.0f * v * LOG2E_)) - 1.0f; }

// ---------------- cp.async helpers ----------------
__device__ __forceinline__ void cpa16(unsigned dst, const void* src) {
    asm volatile("cp.async.cg.shared.global [%0], [%1], 16;" :: "r"(dst), "l"(src));
}
__device__ __forceinline__ void cpa_commit() { asm volatile("cp.async.commit_group;"); }
__device__ __forceinline__ void cpa_wait0()  { asm volatile("cp.async.wait_group 0;"); }

// ---------------- weight prep ----------------
__global__ void prep_weights(const float* __restrict__ eWih, const float* __restrict__ eWhh,
                             const float* __restrict__ dWih, const float* __restrict__ dWhh,
                             const float* __restrict__ U,    const float* __restrict__ Ub,
                             const float* __restrict__ Wl,   const float* __restrict__ Wlb,
                             const float* __restrict__ V) {
    int i = blockIdx.x * 256 + threadIdx.x;
    const int Nwe = 128 * 384, Nwd = 256 * 384, Nge = ENC_ * 384, Ngd = DEC_ * 384;
    const int Nuw = HH * HS;
    if (i < Nwe) {
        int k = i / 384, j = i % 384;
        g_Wenc[i] = (j < GG && k < HH) ? eWhh[j * HH + k] : 0.0f;
        return;
    }
    i -= Nwe;
    if (i < Nwd) {
        int k = i / 384, j = i % 384;
        float v = 0.0f;
        if (j < GG) {
            if (k < 126) v = dWih[j * 142 + 16 + k];
            else if (k == 126) v = dWih[j * 142 + 0];
            else if (k >= 128 && k < 254) v = dWhh[j * HH + (k - 128)];
        }
        g_Wdec[i] = v; return;
    }
    i -= Nwd;
    if (i < Nge) {
        int k = i / 384, j = i % 384;
        g_WgiE[i] = (j < GG) ? eWih[j * ENC_ + k] : 0.0f;
        return;
    }
    i -= Nge;
    if (i < Ngd) {
        int k = i / 384, j = i % 384;
        g_WgiD[i] = (j < GG) ? dWih[j * 142 + 1 + k] : 0.0f;
        return;
    }
    i -= Ngd;
    if (i < Nuw) { int k = i / HS, j = i % HS; g_UWTp[i] = (j < HH) ? U[j * HH + k] : 0.0f; return; }
    i -= Nuw;
    if (i < Nuw) { int k = i / HS, j = i % HS; g_WlTp[i] = (j < HH) ? Wl[j * HH + k] : 0.0f; return; }
    i -= Nuw;
    if (i < HS) { g_Ubp[i] = (i < HH) ? Ub[i] : 0.0f; return; }
    i -= HS;
    if (i < HS) { g_Wlbp[i] = (i < HH) ? Wlb[i] : 0.0f; return; }
    i -= HS;
    if (i < HS) { g_Vp[i] = (i < HH) ? V[i] : 0.0f; }
}

// ---------------- s2h MLP ----------------
__global__ void s2h_kernel(const float* __restrict__ ann,
                           const float* __restrict__ W1, const float* __restrict__ b1,
                           const float* __restrict__ W2, const float* __restrict__ b2,
                           float* __restrict__ h) {
    __shared__ float a[ANN_];
    __shared__ float mid[96];
    int b = blockIdx.x;
    int tid = threadIdx.x;
    if (tid < ANN_) a[tid] = ann[b * ANN_ + tid];
    __syncthreads();
    if (tid < 96) {
        float acc = b1[tid];
        #pragma unroll
        for (int k = 0; k < ANN_; k++) acc += W1[tid * ANN_ + k] * a[k];
        mid[tid] = fmaxf(acc, 0.0f);
    }
    __syncthreads();
    if (tid < HH) {
        float acc = b2[tid];
        #pragma unroll 4
        for (int k = 0; k < 96; k++) acc += W2[tid * 96 + k] * mid[k];
        h[(size_t)b * HS + tid] = acc;
    }
}

// ---------------- gi GEMM ----------------
template <int KD>
__global__ __launch_bounds__(384) void gi_kernel(const float* __restrict__ in,
                                                 const float* __restrict__ Wg,
                                                 float* __restrict__ gi) {
    __shared__ float s_w[KD * 384];
    __shared__ float s_in[KD * 16];
    const int tid = threadIdx.x;
    const int b0 = blockIdx.x * 16;
    for (int i = tid; i < KD * 96; i += 384)
        reinterpret_cast<float4*>(s_w)[i] = reinterpret_cast<const float4*>(Wg)[i];
    for (int i = tid; i < KD * 16; i += 384) {
        int r = i / KD, k = i % KD;
        s_in[k * 16 + r] = in[(size_t)(b0 + r) * KD + k];
    }
    __syncthreads();
    float acc[16];
    #pragma unroll
    for (int r = 0; r < 16; r++) acc[r] = 0.0f;
    #pragma unroll 4
    for (int k = 0; k < KD; k++) {
        float w = s_w[k * 384 + tid];
        const float4* sp = reinterpret_cast<const float4*>(s_in + k * 16);
        float4 v0 = sp[0], v1 = sp[1], v2 = sp[2], v3 = sp[3];
        acc[0]  += w * v0.x; acc[1]  += w * v0.y; acc[2]  += w * v0.z; acc[3]  += w * v0.w;
        acc[4]  += w * v1.x; acc[5]  += w * v1.y; acc[6]  += w * v1.z; acc[7]  += w * v1.w;
        acc[8]  += w * v2.x; acc[9]  += w * v2.y; acc[10] += w * v2.z; acc[11] += w * v2.w;
        acc[12] += w * v3.x; acc[13] += w * v3.y; acc[14] += w * v3.z; acc[15] += w * v3.w;
    }
    if (tid < GG) {
        #pragma unroll
        for (int r = 0; r < 16; r++) gi[(size_t)(b0 + r) * 384 + tid] = acc[r];
    }
}

// ---------------- GRU recurrent step (cp.async, 16-k chunks) ----------------
template <int KP, bool HAS_X, bool IS_DEC>
__global__ __launch_bounds__(384, 2) void gruK(
        const float* __restrict__ h_in,
        const float* __restrict__ x,
        const float* __restrict__ W,      // [KP][384]
        const float* __restrict__ gi,     // [row][384]
        const float* __restrict__ bih, const float* __restrict__ bhh,
        float* __restrict__ h_out,
        const float* __restrict__ h2oW, const float* __restrict__ h2ob,
        float* __restrict__ out) {
    constexpr int NC = KP / 16;
    constexpr int XDP = HAS_X ? 128 : 0;
    constexpr int CHF = 16 * 384;     // floats per chunk
    extern __shared__ float sm[];
    float* s_in  = sm;                 // KP*PIN
    float* pool  = sm + KP * PIN;      // 2*CHF weight buffers, reused for preacts
    float* s_preA = pool;              // 378*15
    float* s_preB = pool + GG * 15;    // 126*15
    float* s_out  = pool + GG * 15 + HH * 15;  // 14

    const int tid = threadIdx.x;
    const int b0 = blockIdx.x * ROWS;
    const int nrow = min(ROWS, BB - b0);

    unsigned pool_sa = (unsigned)__cvta_generic_to_shared(pool);

    // stage chunk 0
    {
        const float* src = W + (size_t)tid * 4;
        #pragma unroll
        for (int v = 0; v < 4; v++)
            cpa16(pool_sa + (unsigned)(tid + 384 * v) * 16u, src + 1536 * v);
        cpa_commit();
    }

    // fill s_in
    if (HAS_X) {
        for (int i = tid; i < 127 * ROWS; i += 384) {
            int r = i / 127, k = i % 127;
            s_in[k * PIN + r] = (r < nrow) ? x[(size_t)(b0 + r) * HS + k] : 0.0f;
        }
        if (tid < ROWS) s_in[127 * PIN + tid] = 0.0f;
    }
    for (int i = tid; i < HH * ROWS; i += 384) {
        int r = i / HH, k = i % HH;
        s_in[(XDP + k) * PIN + r] = (r < nrow) ? h_in[(size_t)(b0 + r) * HS + k] : 0.0f;
    }
    if (tid < 2 * ROWS) {
        int k = tid / ROWS, r = tid % ROWS;
        s_in[(XDP + HH + k) * PIN + r] = 0.0f;
    }

    cpa_wait0();
    __syncthreads();

    float acc[ROWS], accx[ROWS];
    #pragma unroll
    for (int r = 0; r < ROWS; r++) { acc[r] = 0.0f; accx[r] = 0.0f; }

    for (int c = 0; c < NC; c++) {
        const int cur = c & 1;
        if (c + 1 < NC) {
            const float* src = W + (size_t)(c + 1) * CHF + (size_t)tid * 4;
            unsigned dst = pool_sa + (unsigned)((1 - cur) * CHF + tid * 4) * 4u;
            #pragma unroll
            for (int v = 0; v < 4; v++)
                cpa16(dst + (unsigned)v * 384u * 16u, src + 1536 * v);
            cpa_commit();
        }
        const float* wp = pool + cur * CHF + tid;
        const float* ip = s_in + c * 16 * PIN;
        #pragma unroll
        for (int kk = 0; kk < 16; kk++) {
            float w = wp[kk * 384];
            const float* sp = ip + kk * PIN;
            float4 v0 = *reinterpret_cast<const float4*>(sp);
            float4 v1 = *reinterpret_cast<const float4*>(sp + 4);
            float4 v2 = *reinterpret_cast<const float4*>(sp + 8);
            float2 v3 = *reinterpret_cast<const float2*>(sp + 12);
            acc[0]  += w * v0.x; acc[1]  += w * v0.y; acc[2]  += w * v0.z; acc[3]  += w * v0.w;
            acc[4]  += w * v1.x; acc[5]  += w * v1.y; acc[6]  += w * v1.z; acc[7]  += w * v1.w;
            acc[8]  += w * v2.x; acc[9]  += w * v2.y; acc[10] += w * v2.z; acc[11] += w * v2.w;
            acc[12] += w * v3.x; acc[13] += w * v3.y;
        }
        if (HAS_X && c == 7) {
            #pragma unroll
            for (int r = 0; r < ROWS; r++) accx[r] = acc[r];
        }
        if (c + 1 < NC) cpa_wait0();
        __syncthreads();
    }

    // preacts into pool (weight buffers now dead)
    if (tid < GG) {
        #pragma unroll
        for (int r = 0; r < ROWS; r++) s_preA[tid * 15 + r] = acc[r];
    }
    if (HAS_X && tid >= 2 * HH && tid < GG) {
        #pragma unroll
        for (int r = 0; r < ROWS; r++) s_preB[(tid - 2 * HH) * 15 + r] = accx[r];
    }
    if (IS_DEC && tid < ROWS) s_out[tid] = 0.0f;
    __syncthreads();

    for (int i = tid; i < ROWS * 128; i += 384) {
        int r = i >> 7;
        int j = i & 127;
        if (r >= nrow) continue;
        if (j < HH) {
            const float* gir = gi + (size_t)(b0 + r) * 384;
            float pr = s_preA[j * 15 + r]        + gir[j]      + bih[j]      + bhh[j];
            float pz = s_preA[(HH + j) * 15 + r] + gir[HH + j] + bih[HH + j] + bhh[HH + j];
            float nx, nh;
            if (HAS_X) {
                float sx = s_preB[j * 15 + r];
                nx = sx + gir[2 * HH + j] + bih[2 * HH + j];
                nh = s_preA[(2 * HH + j) * 15 + r] - sx + bhh[2 * HH + j];
            } else {
                nx = gir[2 * HH + j] + bih[2 * HH + j];
                nh = s_preA[(2 * HH + j) * 15 + r] + bhh[2 * HH + j];
            }
            float rg = sigf(pr);
            float zg = sigf(pz);
            float nn = tanhp(nx + rg * nh);
            float hv = s_in[(XDP + j) * PIN + r];
            float hnew = (1.0f - zg) * nn + zg * hv;
            h_out[(size_t)(b0 + r) * HS + j] = hnew;
            if (IS_DEC) atomicAdd(&s_out[r], hnew * h2oW[j]);
        } else if (!IS_DEC) {
            h_out[(size_t)(b0 + r) * HS + j] = 0.0f;
        }
    }
    if (IS_DEC) {
        __syncthreads();
        if (tid < nrow) out[b0 + tid] = s_out[tid] + h2ob[0];
    }
}

// ---------------- dense [rows x 126] @ [126 x 128] + bias (Uo and Wh) --------
__global__ __launch_bounds__(256, 2) void uo_kernel(const float* __restrict__ in,
                                                    const float* __restrict__ Wp,
                                                    const float* __restrict__ biasp,
                                                    float* __restrict__ out) {
    constexpr int P2 = 36;
    extern __shared__ float sm[];
    float* s_w  = sm;
    float* s_in = sm + HH * HS;
    const int tid = threadIdx.x;
    const int b0 = blockIdx.x * 32;

    {
        const float4* src = reinterpret_cast<const float4*>(Wp);
        float4* dst = reinterpret_cast<float4*>(s_w);
        for (int v = tid; v < HH * HS / 4; v += 256) dst[v] = src[v];
    }
    for (int idx = tid; idx < HH * 32; idx += 256) {
        int r = idx / HH, k = idx % HH;
        s_in[k * P2 + r] = in[(size_t)(b0 + r) * HS + k];
    }
    __syncthreads();

    const int j = tid & 127;
    const int half = tid >> 7;
    float acc[16];
    #pragma unroll
    for (int r = 0; r < 16; r++) acc[r] = 0.0f;
    #pragma unroll 2
    for (int k = 0; k < HH; k++) {
        float w = s_w[k * HS + j];
        const float4* sp = reinterpret_cast<const float4*>(s_in + k * P2 + half * 16);
        float4 v0 = sp[0], v1 = sp[1], v2 = sp[2], v3 = sp[3];
        acc[0]  += w * v0.x; acc[1]  += w * v0.y; acc[2]  += w * v0.z; acc[3]  += w * v0.w;
        acc[4]  += w * v1.x; acc[5]  += w * v1.y; acc[6]  += w * v1.z; acc[7]  += w * v1.w;
        acc[8]  += w * v2.x; acc[9]  += w * v2.y; acc[10] += w * v2.z; acc[11] += w * v2.w;
        acc[12] += w * v3.x; acc[13] += w * v3.y; acc[14] += w * v3.z; acc[15] += w * v3.w;
    }
    float bj = biasp[j];
    #pragma unroll
    for (int r = 0; r < 16; r++)
        out[(size_t)(b0 + half * 16 + r) * HS + j] = acc[r] + bj;
}

// ---------------- scores: grid split over (b-tile, t-tile) ----------------
__global__ __launch_bounds__(256) void score_kernel(
        const float* __restrict__ Uo, const float* __restrict__ Wh,
        const float* __restrict__ Vp, const float* __restrict__ Vb,
        float* __restrict__ scores) {
    const int tid = threadIdx.x;
    const int warp = tid >> 5, lane = tid & 31;
    const int g = lane >> 3, q = lane & 7;
    const int bi = blockIdx.x & 127;
    const int t0 = (blockIdx.x >> 7) * 14;
    const int row = bi * 32 + warp * 4 + g;

    float4 wh[4], vv[4];
    #pragma unroll
    for (int m = 0; m < 4; m++) {
        wh[m] = *(reinterpret_cast<const float4*>(Wh + (size_t)row * HS) + q + 8 * m);
        vv[m] = *(reinterpret_cast<const float4*>(Vp) + q + 8 * m);
    }
    const float vb = Vb[0];

    #pragma unroll 2
    for (int t = t0; t < t0 + 14; t++) {
        const float4* up = reinterpret_cast<const float4*>(Uo + ((size_t)t * BB + row) * HS);
        float a = 0.0f;
        #pragma unroll
        for (int m = 0; m < 4; m++) {
            float4 u = up[q + 8 * m];
            a += tanha(u.x + wh[m].x) * vv[m].x;
            a += tanha(u.y + wh[m].y) * vv[m].y;
            a += tanha(u.z + wh[m].z) * vv[m].z;
            a += tanha(u.w + wh[m].w) * vv[m].w;
        }
        a += __shfl_xor_sync(0xffffffffu, a, 1);
        a += __shfl_xor_sync(0xffffffffu, a, 2);
        a += __shfl_xor_sync(0xffffffffu, a, 4);
        if (q == 0) scores[(size_t)t * BB + row] = a + vb;
    }
}

// ---------------- softmax + context + x assembly ----------------
__global__ __launch_bounds__(128) void ctx_kernel(
        const float* __restrict__ scores, const float* __restrict__ enc_out,
        const float* __restrict__ enc_data, const float* __restrict__ outbuf,
        float* __restrict__ x, int step) {
    __shared__ float sal[TT * 8];
    const int tid = threadIdx.x;
    const int warp = tid >> 5, lane = tid & 31;
    const int b0 = blockIdx.x * 8;

    if (tid < 8) {
        int b = b0 + tid;
        float mx = -1e30f;
        for (int t = 0; t < TT; t++) {
            float v = scores[(size_t)t * BB + b];
            sal[t * 8 + tid] = v;
            mx = fmaxf(mx, v);
        }
        float sum = 0.0f;
        for (int t = 0; t < TT; t++) {
            float e = ex2f((sal[t * 8 + tid] - mx) * LOG2E_);
            sal[t * 8 + tid] = e;
            sum += e;
        }
        float inv = rcpf(sum);
        for (int t = 0; t < TT; t++) sal[t * 8 + tid] *= inv;
    }
    __syncthreads();

    const int r0 = 2 * warp, r1 = r0 + 1;
    float4 a0 = {0.f, 0.f, 0.f, 0.f}, a1 = {0.f, 0.f, 0.f, 0.f};
    #pragma unroll 2
    for (int t = 0; t < TT; t++) {
        float al0 = sal[t * 8 + r0], al1 = sal[t * 8 + r1];
        float4 e0 = *(reinterpret_cast<const float4*>(enc_out + ((size_t)t * BB + b0 + r0) * HS) + lane);
        float4 e1 = *(reinterpret_cast<const float4*>(enc_out + ((size_t)t * BB + b0 + r1) * HS) + lane);
        a0.x += al0 * e0.x; a0.y += al0 * e0.y; a0.z += al0 * e0.z; a0.w += al0 * e0.w;
        a1.x += al1 * e1.x; a1.y += al1 * e1.y; a1.z += al1 * e1.z; a1.w += al1 * e1.w;
    }
    *(reinterpret_cast<float4*>(x + (size_t)(b0 + r0) * HS) + lane) = a0;
    *(reinterpret_cast<float4*>(x + (size_t)(b0 + r1) * HS) + lane) = a1;
    __syncthreads();
    if (tid < 8) {
        float prev = (step == 0) ? enc_data[((size_t)(TT - 1) * BB + b0 + tid) * ENC_]
                                 : outbuf[(size_t)(step - 1) * BB + b0 + tid];
        x[(size_t)(b0 + tid) * HS + 126] = prev;
    }
}

// ---------------- host side ----------------
extern "C" void kernel_launch(void* const* d_in, const int* in_sizes, int n_in,
                              void* d_out, int out_size) {
    const float* ann      = (const float*)d_in[0];
    const float* enc_data = (const float*)d_in[1];
    const float* dec_data = (const float*)d_in[2];
    const float* s2h_W1   = (const float*)d_in[3];
    const float* s2h_b1   = (const float*)d_in[4];
    const float* s2h_W2   = (const float*)d_in[5];
    const float* s2h_b2   = (const float*)d_in[6];
    const float* enc_Wih  = (const float*)d_in[7];
    const float* enc_Whh  = (const float*)d_in[8];
    const float* enc_bih  = (const float*)d_in[9];
    const float* enc_bhh  = (const float*)d_in[10];
    const float* dec_Wih  = (const float*)d_in[11];
    const float* dec_Whh  = (const float*)d_in[12];
    const float* dec_bih  = (const float*)d_in[13];
    const float* dec_bhh  = (const float*)d_in[14];
    const float* U_W      = (const float*)d_in[15];
    const float* U_b      = (const float*)d_in[16];
    const float* Wl_W     = (const float*)d_in[17];
    const float* Wl_b     = (const float*)d_in[18];
    const float* V_W      = (const float*)d_in[19];
    const float* V_b      = (const float*)d_in[20];
    const float* h2o_W    = (const float*)d_in[21];
    const float* h2o_b    = (const float*)d_in[22];
    float* outp = (float*)d_out;

    float *h0, *h1, *enc_out, *Uo, *Wh, *scores, *x, *giE, *giD;
    float *Wenc, *Wdec, *WgiE, *WgiD, *UWTp, *WlTp, *Ubp, *Wlbp, *Vp;
    cudaGetSymbolAddress((void**)&h0, g_h0);
    cudaGetSymbolAddress((void**)&h1, g_h1);
    cudaGetSymbolAddress((void**)&enc_out, g_enc_out);
    cudaGetSymbolAddress((void**)&Uo, g_Uo);
    cudaGetSymbolAddress((void**)&Wh, g_Wh);
    cudaGetSymbolAddress((void**)&scores, g_scores);
    cudaGetSymbolAddress((void**)&x, g_x);
    cudaGetSymbolAddress((void**)&giE, g_giE);
    cudaGetSymbolAddress((void**)&giD, g_giD);
    cudaGetSymbolAddress((void**)&Wenc, g_Wenc);
    cudaGetSymbolAddress((void**)&Wdec, g_Wdec);
    cudaGetSymbolAddress((void**)&WgiE, g_WgiE);
    cudaGetSymbolAddress((void**)&WgiD, g_WgiD);
    cudaGetSymbolAddress((void**)&UWTp, g_UWTp);
    cudaGetSymbolAddress((void**)&WlTp, g_WlTp);
    cudaGetSymbolAddress((void**)&Ubp, g_Ubp);
    cudaGetSymbolAddress((void**)&Wlbp, g_Wlbp);
    cudaGetSymbolAddress((void**)&Vp, g_Vp);

    const size_t sm_enc = (size_t)(128 * PIN + 2 * 16 * 384) * 4;   // 59392
    const size_t sm_dec = (size_t)(256 * PIN + 2 * 16 * 384) * 4;   // 69632
    const size_t sm_uo  = (size_t)(HH * HS + HH * 36) * 4;
    cudaFuncSetAttribute((const void*)gruK<128, false, false>,
                         cudaFuncAttributeMaxDynamicSharedMemorySize, (int)sm_enc);
    cudaFuncSetAttribute((const void*)gruK<256, true, true>,
                         cudaFuncAttributeMaxDynamicSharedMemorySize, (int)sm_dec);
    cudaFuncSetAttribute((const void*)uo_kernel,
                         cudaFuncAttributeMaxDynamicSharedMemorySize, (int)sm_uo);

    const int total_w = 128 * 384 + 256 * 384 + ENC_ * 384 + DEC_ * 384
                      + 2 * HH * HS + 3 * HS;
    prep_weights<<<(total_w + 255) / 256, 256>>>(enc_Wih, enc_Whh, dec_Wih, dec_Whh,
                                                 U_W, U_b, Wl_W, Wl_b, V_W);

    s2h_kernel<<<BB, 128>>>(ann, s2h_W1, s2h_b1, s2h_W2, s2h_b2, h0);

    gi_kernel<ENC_><<<TT * BB / 16, 384>>>(enc_data, WgiE, giE);
    gi_kernel<DEC_><<<NSTEPS * BB / 16, 384>>>(dec_data, WgiD, giD);

    for (int t = 0; t < TT; t++) {
        const float* hin = (t == 0) ? h0 : enc_out + (size_t)(t - 1) * BB * HS;
        gruK<128, false, false><<<NBLK, 384, sm_enc>>>(
            hin, nullptr, Wenc, giE + (size_t)t * BB * 384, enc_bih, enc_bhh,
            enc_out + (size_t)t * BB * HS, nullptr, nullptr, nullptr);
    }

    uo_kernel<<<TT * BB / 32, 256, sm_uo>>>(enc_out, UWTp, Ubp, Uo);

    const float* enc_last = enc_out + (size_t)(TT - 1) * BB * HS;
    for (int s = 0; s < NSTEPS; s++) {
        const float* hcur = (s == 0) ? enc_last : ((s & 1) ? h0 : h1);
        float* hnext      = (s & 1) ? h1 : h0;
        uo_kernel<<<BB / 32, 256, sm_uo>>>(hcur, WlTp, Wlbp, Wh);
        score_kernel<<<128 * 4, 256>>>(Uo, Wh, Vp, V_b, scores);
        ctx_kernel<<<BB / 8, 128>>>(scores, enc_out, enc_data, outp, x, s);
        gruK<256, true, true><<<NBLK, 384, sm_dec>>>(
            hcur, x, Wdec, giD + (size_t)s * BB * 384, dec_bih, dec_bhh,
            hnext, h2o_W, h2o_b, outp + (size_t)s * BB);
    }
}